// round 2
// baseline (speedup 1.0000x reference)
#include <cuda_runtime.h>
#include <math.h>

// Problem constants
#define D_MODEL 2048
#define BATCH   2
#define SEQ     2048
#define MROWS   (BATCH * SEQ)   // 4096

// ---------------------------------------------------------------------------
// Device scratch (allocation-free contract: __device__ globals)
// ---------------------------------------------------------------------------
__device__ float g_Q[(size_t)MROWS * D_MODEL];
__device__ float g_K[(size_t)MROWS * D_MODEL];
__device__ float g_V[(size_t)MROWS * D_MODEL];
__device__ float g_S[(size_t)BATCH * SEQ * SEQ];
__device__ float g_O[(size_t)MROWS * D_MODEL];

// ---------------------------------------------------------------------------
// Tiled SGEMM: C = alpha * A @ B   (or A @ B^T when TRANS_B)
// A: M x K row-major. B: K x N row-major (NN) or N x K row-major (NT).
// Tiles: 128x128x16, 256 threads, 8x8 per thread.
// All dims are multiples of the tile sizes for this problem -> no bounds checks.
// blockIdx.z selects batch via element strides sA/sB/sC.
// ---------------------------------------------------------------------------
#define BM 128
#define BN 128
#define BK 16
#define TM 8
#define TN 8

template<bool TRANS_B>
__global__ __launch_bounds__(256)
void gemm_kernel(const float* __restrict__ A,
                 const float* __restrict__ B,
                 float* __restrict__ C,
                 int M, int N, int K,
                 long sA, long sB, long sC,
                 float alpha)
{
    __shared__ float As[BK][BM + 4];
    __shared__ float Bs[BK][BN + 4];

    const float* Ab = A + blockIdx.z * sA;
    const float* Bb = B + blockIdx.z * sB;
    float*       Cb = C + blockIdx.z * sC;

    const int tid      = threadIdx.x;
    const int blockRow = blockIdx.y * BM;
    const int blockCol = blockIdx.x * BN;

    // A-load (and NT B-load) indices: 128 rows x 16 k, float4 along K
    const int arow = tid >> 2;          // 0..63 (+64 second pass)
    const int acol = (tid & 3) << 2;    // 0,4,8,12

    // NN B-load indices: 16 k-rows x 128 cols, float4 along N
    const int bkrow = tid >> 5;         // 0..7 (+8 second pass)
    const int bcol  = (tid & 31) << 2;  // 0..124

    const int ty = tid >> 4;            // 0..15
    const int tx = tid & 15;            // 0..15

    float acc[TM][TN];
    #pragma unroll
    for (int i = 0; i < TM; i++)
        #pragma unroll
        for (int j = 0; j < TN; j++)
            acc[i][j] = 0.0f;

    for (int k0 = 0; k0 < K; k0 += BK) {
        // Load A tile (transpose into smem: As[k][m])
        #pragma unroll
        for (int p = 0; p < 2; p++) {
            int r = arow + p * 64;
            float4 v = *reinterpret_cast<const float4*>(
                &Ab[(long)(blockRow + r) * K + k0 + acol]);
            As[acol + 0][r] = v.x;
            As[acol + 1][r] = v.y;
            As[acol + 2][r] = v.z;
            As[acol + 3][r] = v.w;
        }
        if (TRANS_B) {
            // B is N x K row-major: same transposed-load pattern as A
            #pragma unroll
            for (int p = 0; p < 2; p++) {
                int r = arow + p * 64;
                float4 v = *reinterpret_cast<const float4*>(
                    &Bb[(long)(blockCol + r) * K + k0 + acol]);
                Bs[acol + 0][r] = v.x;
                Bs[acol + 1][r] = v.y;
                Bs[acol + 2][r] = v.z;
                Bs[acol + 3][r] = v.w;
            }
        } else {
            // B is K x N row-major: direct vectorized copy
            #pragma unroll
            for (int p = 0; p < 2; p++) {
                int kr = bkrow + p * 8;
                float4 v = *reinterpret_cast<const float4*>(
                    &Bb[(long)(k0 + kr) * N + blockCol + bcol]);
                *reinterpret_cast<float4*>(&Bs[kr][bcol]) = v;
            }
        }
        __syncthreads();

        #pragma unroll
        for (int kk = 0; kk < BK; kk++) {
            float a[TM], b[TN];
            #pragma unroll
            for (int i = 0; i < TM; i++) a[i] = As[kk][ty * TM + i];
            #pragma unroll
            for (int j = 0; j < TN; j++) b[j] = Bs[kk][tx * TN + j];
            #pragma unroll
            for (int i = 0; i < TM; i++)
                #pragma unroll
                for (int j = 0; j < TN; j++)
                    acc[i][j] = fmaf(a[i], b[j], acc[i][j]);
        }
        __syncthreads();
    }

    // Epilogue: alpha scale, vectorized store
    #pragma unroll
    for (int i = 0; i < TM; i++) {
        long rowOff = (long)(blockRow + ty * TM + i) * N + blockCol + tx * TN;
        #pragma unroll
        for (int j = 0; j < TN; j += 4) {
            float4 v;
            v.x = alpha * acc[i][j + 0];
            v.y = alpha * acc[i][j + 1];
            v.z = alpha * acc[i][j + 2];
            v.w = alpha * acc[i][j + 3];
            *reinterpret_cast<float4*>(&Cb[rowOff + j]) = v;
        }
    }
}

// ---------------------------------------------------------------------------
// Row softmax over SEQ=2048 elements. One block (256 threads) per row.
// ---------------------------------------------------------------------------
__global__ __launch_bounds__(256)
void softmax_kernel(float* __restrict__ Sm)
{
    float4* row = reinterpret_cast<float4*>(Sm + (size_t)blockIdx.x * SEQ);
    const int tid  = threadIdx.x;
    const int lane = tid & 31;
    const int wid  = tid >> 5;

    float4 a = row[tid];
    float4 b = row[tid + 256];

    float m = fmaxf(fmaxf(fmaxf(a.x, a.y), fmaxf(a.z, a.w)),
                    fmaxf(fmaxf(b.x, b.y), fmaxf(b.z, b.w)));
    #pragma unroll
    for (int o = 16; o > 0; o >>= 1)
        m = fmaxf(m, __shfl_xor_sync(0xffffffffu, m, o));

    __shared__ float redm[8];
    __shared__ float reds[8];
    if (lane == 0) redm[wid] = m;
    __syncthreads();
    float bm = fmaxf(fmaxf(fmaxf(redm[0], redm[1]), fmaxf(redm[2], redm[3])),
                     fmaxf(fmaxf(redm[4], redm[5]), fmaxf(redm[6], redm[7])));

    a.x = expf(a.x - bm); a.y = expf(a.y - bm);
    a.z = expf(a.z - bm); a.w = expf(a.w - bm);
    b.x = expf(b.x - bm); b.y = expf(b.y - bm);
    b.z = expf(b.z - bm); b.w = expf(b.w - bm);

    float s = a.x + a.y + a.z + a.w + b.x + b.y + b.z + b.w;
    #pragma unroll
    for (int o = 16; o > 0; o >>= 1)
        s += __shfl_xor_sync(0xffffffffu, s, o);
    if (lane == 0) reds[wid] = s;
    __syncthreads();
    float bs = reds[0] + reds[1] + reds[2] + reds[3]
             + reds[4] + reds[5] + reds[6] + reds[7];

    float inv = 1.0f / bs;
    a.x *= inv; a.y *= inv; a.z *= inv; a.w *= inv;
    b.x *= inv; b.y *= inv; b.z *= inv; b.w *= inv;

    row[tid]       = a;
    row[tid + 256] = b;
}

// ---------------------------------------------------------------------------
// Launch: Q/K/V proj -> scores (NT, scaled) -> softmax -> attn@V -> out proj
// ---------------------------------------------------------------------------
extern "C" void kernel_launch(void* const* d_in, const int* in_sizes, int n_in,
                              void* d_out, int out_size)
{
    (void)in_sizes; (void)n_in; (void)out_size;
    const float* x  = (const float*)d_in[0];
    const float* Wq = (const float*)d_in[1];
    const float* Wk = (const float*)d_in[2];
    const float* Wv = (const float*)d_in[3];
    const float* Wo = (const float*)d_in[4];
    float* out = (float*)d_out;

    float *Q, *K, *V, *Sm, *O;
    cudaGetSymbolAddress((void**)&Q,  g_Q);
    cudaGetSymbolAddress((void**)&K,  g_K);
    cudaGetSymbolAddress((void**)&V,  g_V);
    cudaGetSymbolAddress((void**)&Sm, g_S);
    cudaGetSymbolAddress((void**)&O,  g_O);

    const dim3 blk(256);
    const dim3 gProj(D_MODEL / BN, MROWS / BM, 1);        // (16, 32)
    const dim3 gScore(SEQ / BN, SEQ / BM, BATCH);         // (16, 16, 2)
    const dim3 gPV(D_MODEL / BN, SEQ / BM, BATCH);        // (16, 16, 2)

    const long sQKV = (long)SEQ * D_MODEL;
    const long sSS  = (long)SEQ * SEQ;
    const float scale = 1.0f / sqrtf((float)D_MODEL);

    // Projections: (4096 x 2048) = x @ W
    gemm_kernel<false><<<gProj, blk>>>(x, Wq, Q, MROWS, D_MODEL, D_MODEL, 0, 0, 0, 1.0f);
    gemm_kernel<false><<<gProj, blk>>>(x, Wk, K, MROWS, D_MODEL, D_MODEL, 0, 0, 0, 1.0f);
    gemm_kernel<false><<<gProj, blk>>>(x, Wv, V, MROWS, D_MODEL, D_MODEL, 0, 0, 0, 1.0f);

    // scores[b] = scale * Q[b] @ K[b]^T
    gemm_kernel<true><<<gScore, blk>>>(Q, K, Sm, SEQ, SEQ, D_MODEL, sQKV, sQKV, sSS, scale);

    // row softmax over all B*S rows
    softmax_kernel<<<BATCH * SEQ, blk>>>(Sm);

    // O[b] = attn[b] @ V[b]
    gemm_kernel<false><<<gPV, blk>>>(Sm, V, O, SEQ, D_MODEL, SEQ, sSS, sQKV, sQKV, 1.0f);

    // out = O @ W_o
    gemm_kernel<false><<<gProj, blk>>>(O, Wo, out, MROWS, D_MODEL, D_MODEL, 0, 0, 0, 1.0f);
}

// round 4
// speedup vs baseline: 1.8167x; 1.8167x over previous
#include <cuda_runtime.h>
#include <cuda_bf16.h>
#include <math.h>
#include <stdint.h>

#define D_MODEL 2048
#define BATCH   2
#define SEQ     2048
#define MROWS   (BATCH * SEQ)                 // 4096
#define ELEMS   ((size_t)MROWS * D_MODEL)     // 8388608
#define WELEMS  ((size_t)D_MODEL * D_MODEL)   // 4194304

// ---------------------------------------------------------------------------
// Device scratch (allocation-free contract)
// ---------------------------------------------------------------------------
__device__ __nv_bfloat16 g_xh[ELEMS],  g_xl[ELEMS];
__device__ __nv_bfloat16 g_Wth[4 * WELEMS], g_Wtl[4 * WELEMS];  // W^T hi/lo, [n][k]
__device__ __nv_bfloat16 g_Qh[ELEMS],  g_Ql[ELEMS];
__device__ __nv_bfloat16 g_Kh[ELEMS],  g_Kl[ELEMS];
__device__ __nv_bfloat16 g_Vth[ELEMS], g_Vtl[ELEMS];            // V^T: [b][d][s]
__device__ float         g_S [(size_t)BATCH * SEQ * SEQ];
__device__ __nv_bfloat16 g_Ph[(size_t)BATCH * SEQ * SEQ], g_Pl[(size_t)BATCH * SEQ * SEQ];
__device__ __nv_bfloat16 g_Oh[ELEMS],  g_Ol[ELEMS];

// ---------------------------------------------------------------------------
// Helpers
// ---------------------------------------------------------------------------
__device__ __forceinline__ uint32_t s2u(const void* p) {
    return (uint32_t)__cvta_generic_to_shared(p);
}
__device__ __forceinline__ void cp16(uint32_t dst, const void* src) {
    asm volatile("cp.async.cg.shared.global [%0], [%1], 16;\n"
                 :: "r"(dst), "l"(__cvta_generic_to_global(src)));
}
__device__ __forceinline__ void cp_commit() { asm volatile("cp.async.commit_group;"); }
template<int N> __device__ __forceinline__ void cp_wait() {
    asm volatile("cp.async.wait_group %0;" :: "n"(N));
}
__device__ __forceinline__ void ldm_x4(uint32_t* r, uint32_t addr) {
    asm volatile("ldmatrix.sync.aligned.m8n8.x4.shared.b16 {%0,%1,%2,%3}, [%4];"
                 : "=r"(r[0]), "=r"(r[1]), "=r"(r[2]), "=r"(r[3]) : "r"(addr));
}
__device__ __forceinline__ void mma_bf16(float* d, const uint32_t* a,
                                         uint32_t b0, uint32_t b1) {
    asm volatile(
        "mma.sync.aligned.m16n8k16.row.col.f32.bf16.bf16.f32 "
        "{%0,%1,%2,%3}, {%4,%5,%6,%7}, {%8,%9}, {%0,%1,%2,%3};"
        : "+f"(d[0]), "+f"(d[1]), "+f"(d[2]), "+f"(d[3])
        : "r"(a[0]), "r"(a[1]), "r"(a[2]), "r"(a[3]), "r"(b0), "r"(b1));
}
__device__ __forceinline__ void bsplit(float v, unsigned short& h, unsigned short& l) {
    __nv_bfloat16 bh = __float2bfloat16(v);
    float fh = __bfloat162float(bh);
    __nv_bfloat16 bl = __float2bfloat16(v - fh);
    h = *reinterpret_cast<unsigned short*>(&bh);
    l = *reinterpret_cast<unsigned short*>(&bl);
}

// ---------------------------------------------------------------------------
// mma.sync GEMM: D[m,n] = sum_k (Ah+Al)[m,k] * (Bh+Bl)[n,k]  (3-term split)
// A: [M,2048] row-major bf16 ; B: [N,2048] row-major bf16 (K-major "B^T").
// CTA tile 128x128, 8 warps (warp tile 32x64), K-chunk 32, 4-stage cp.async.
// Row stride in smem = 80 B (64 B data + 16 B pad) -> conflict-free ldmatrix.
// EPI: 0 = fp32*alpha -> Cf ; 1 = bf16 hi/lo split -> Ch/Cl ;
//      2 = split + per-batch transpose (V^T): Ch/Cl[b][n][s], b = m>>11.
// Global row stride is 2048 elements for every operand in this problem.
// ---------------------------------------------------------------------------
#define KC     32
#define STAGES 4
#define ROWB   80
#define TILEB  (128 * ROWB)      // 10240 per operand array
#define STG    (4 * TILEB)       // 40960 per stage (Ah, Al, Bh, Bl)
#define NCH    (2048 / KC)       // 64
#define SMEM_SZ (STAGES * STG)   // 163840

template<int EPI>
__global__ void __launch_bounds__(256, 1)
gemm_mma(const __nv_bfloat16* __restrict__ Ah, const __nv_bfloat16* __restrict__ Al,
         const __nv_bfloat16* __restrict__ Bh, const __nv_bfloat16* __restrict__ Bl,
         float* __restrict__ Cf, __nv_bfloat16* __restrict__ Ch,
         __nv_bfloat16* __restrict__ Cl,
         long sA, long sB, long sC, float alpha)
{
    extern __shared__ char smem[];
    const uint32_t sb = s2u(smem);
    const int tid  = threadIdx.x;
    const int warp = tid >> 5;
    const int lane = tid & 31;
    const int wm   = warp >> 1;          // 0..3  (M)
    const int wn   = warp & 1;           // 0..1  (N)

    const long rowA0 = (long)blockIdx.y * 128;
    const long colB0 = (long)blockIdx.x * 128;
    const __nv_bfloat16* A0h = Ah + (long)blockIdx.z * sA;
    const __nv_bfloat16* A0l = Al + (long)blockIdx.z * sA;
    const __nv_bfloat16* B0h = Bh + (long)blockIdx.z * sB;
    const __nv_bfloat16* B0l = Bl + (long)blockIdx.z * sB;

    // per-thread load coords: 512 16B segments per array, 2 per thread
    const int lr0 = tid >> 1;            // row for p=0  (0..127)
    const int ls0 = (tid & 1) << 1;      // seg 0 or 2
    auto load_chunk = [&](int chunk, int stage) {
        const int k0 = chunk * KC;
        const uint32_t base = sb + (uint32_t)stage * STG;
        #pragma unroll
        for (int p = 0; p < 2; p++) {
            int r  = lr0;
            int sg = ls0 + p;            // 0..3
            uint32_t d = base + (uint32_t)(r * ROWB + sg * 16);
            long gA = (rowA0 + r) * 2048 + k0 + sg * 8;
            long gB = (colB0 + r) * 2048 + k0 + sg * 8;
            cp16(d,             A0h + gA);
            cp16(d + TILEB,     A0l + gA);
            cp16(d + 2 * TILEB, B0h + gB);
            cp16(d + 3 * TILEB, B0l + gB);
        }
    };

    // ldmatrix per-thread address pieces
    const int fr  = lane & 15;           // row within 16-row tile pair
    const int fc  = (lane >> 4) << 4;    // byte col 0 or 16
    const uint32_t aoff = (uint32_t)((wm * 32 + fr) * ROWB + fc);
    const uint32_t boff = (uint32_t)((wn * 64 + fr) * ROWB + fc);

    float acc[2][8][4];
    #pragma unroll
    for (int i = 0; i < 2; i++)
        #pragma unroll
        for (int j = 0; j < 8; j++)
            #pragma unroll
            for (int c = 0; c < 4; c++)
                acc[i][j][c] = 0.0f;

    // prologue
    load_chunk(0, 0); cp_commit();
    load_chunk(1, 1); cp_commit();
    load_chunk(2, 2); cp_commit();

    for (int i = 0; i < NCH; i++) {
        if (i < NCH - 2)      cp_wait<2>();
        else if (i == NCH - 2) cp_wait<1>();
        else                   cp_wait<0>();
        __syncthreads();

        if (i + STAGES - 1 < NCH) {
            load_chunk(i + STAGES - 1, (i + STAGES - 1) & (STAGES - 1));
            cp_commit();
        }

        const uint32_t base = sb + (uint32_t)(i & (STAGES - 1)) * STG;
        #pragma unroll
        for (int ks = 0; ks < 2; ks++) {
            uint32_t aH[2][4], aL[2][4], bH[4][4], bL[4][4];
            #pragma unroll
            for (int mf = 0; mf < 2; mf++) {
                uint32_t ad = base + aoff + (uint32_t)(mf * 16 * ROWB + ks * 32);
                ldm_x4(aH[mf], ad);
                ldm_x4(aL[mf], ad + TILEB);
            }
            #pragma unroll
            for (int nq = 0; nq < 4; nq++) {
                uint32_t bd = base + 2 * TILEB + boff
                            + (uint32_t)(nq * 16 * ROWB + ks * 32);
                ldm_x4(bH[nq], bd);
                ldm_x4(bL[nq], bd + TILEB);
            }
            #pragma unroll
            for (int mf = 0; mf < 2; mf++)
                #pragma unroll
                for (int j = 0; j < 8; j++) {
                    const int nq = j >> 1, o = j & 1;
                    mma_bf16(acc[mf][j], aH[mf], bH[nq][o], bH[nq][o + 2]);
                    mma_bf16(acc[mf][j], aH[mf], bL[nq][o], bL[nq][o + 2]);
                    mma_bf16(acc[mf][j], aL[mf], bH[nq][o], bH[nq][o + 2]);
                }
        }
    }
    __syncthreads();

    // ------------------------------- epilogue -------------------------------
    const int er = lane >> 2;            // 0..7
    const int ec = (lane & 3) << 1;      // 0,2,4,6
    #pragma unroll
    for (int mf = 0; mf < 2; mf++) {
        const long m0 = rowA0 + wm * 32 + mf * 16 + er;   // and +8
        #pragma unroll
        for (int j = 0; j < 8; j++) {
            const long n = colB0 + wn * 64 + j * 8 + ec;
            if (EPI == 0) {
                float* C = Cf + (long)blockIdx.z * sC;
                float2 v0 = make_float2(alpha * acc[mf][j][0], alpha * acc[mf][j][1]);
                float2 v1 = make_float2(alpha * acc[mf][j][2], alpha * acc[mf][j][3]);
                *reinterpret_cast<float2*>(C + m0 * 2048 + n)       = v0;
                *reinterpret_cast<float2*>(C + (m0 + 8) * 2048 + n) = v1;
            } else if (EPI == 1) {
                unsigned short* CH = (unsigned short*)Ch + (long)blockIdx.z * sC;
                unsigned short* CL = (unsigned short*)Cl + (long)blockIdx.z * sC;
                ushort2 H, L;
                bsplit(acc[mf][j][0], H.x, L.x);
                bsplit(acc[mf][j][1], H.y, L.y);
                *reinterpret_cast<ushort2*>(CH + m0 * 2048 + n) = H;
                *reinterpret_cast<ushort2*>(CL + m0 * 2048 + n) = L;
                bsplit(acc[mf][j][2], H.x, L.x);
                bsplit(acc[mf][j][3], H.y, L.y);
                *reinterpret_cast<ushort2*>(CH + (m0 + 8) * 2048 + n) = H;
                *reinterpret_cast<ushort2*>(CL + (m0 + 8) * 2048 + n) = L;
            } else {
                // V^T scatter: element (m, n) -> [b][n][s], b = m>>11, s = m&2047
                unsigned short* CH = (unsigned short*)Ch;
                unsigned short* CL = (unsigned short*)Cl;
                #pragma unroll
                for (int c = 0; c < 4; c++) {
                    long m = m0 + (c >> 1) * 8;
                    long nn = n + (c & 1);
                    long b = m >> 11, sl = m & 2047;
                    unsigned short h, l;
                    bsplit(acc[mf][j][c], h, l);
                    CH[b * 4194304 + nn * 2048 + sl] = h;
                    CL[b * 4194304 + nn * 2048 + sl] = l;
                }
            }
        }
    }
}

// ---------------------------------------------------------------------------
// x -> hi/lo bf16 split (elementwise, float4)
// ---------------------------------------------------------------------------
__global__ void __launch_bounds__(256)
split_kernel(const float* __restrict__ in, __nv_bfloat16* __restrict__ hi,
             __nv_bfloat16* __restrict__ lo)
{
    size_t i = ((size_t)blockIdx.x * 256 + threadIdx.x) * 4;
    float4 v = *reinterpret_cast<const float4*>(in + i);
    ushort4 H, L;
    bsplit(v.x, H.x, L.x); bsplit(v.y, H.y, L.y);
    bsplit(v.z, H.z, L.z); bsplit(v.w, H.w, L.w);
    *reinterpret_cast<ushort4*>((unsigned short*)hi + i) = H;
    *reinterpret_cast<ushort4*>((unsigned short*)lo + i) = L;
}

// ---------------------------------------------------------------------------
// W [k][n] fp32 -> W^T [n][k] bf16 hi/lo (tiled transpose)
// ---------------------------------------------------------------------------
__global__ void __launch_bounds__(256)
tsplit_kernel(const float* __restrict__ W, __nv_bfloat16* __restrict__ Th,
              __nv_bfloat16* __restrict__ Tl)
{
    __shared__ float t[32][33];
    const int bx = blockIdx.x * 32, by = blockIdx.y * 32;
    const int tx = threadIdx.x & 31, ty = threadIdx.x >> 5;   // 32 x 8
    #pragma unroll
    for (int rr = 0; rr < 4; rr++)
        t[ty + 8 * rr][tx] = W[(size_t)(by + ty + 8 * rr) * 2048 + bx + tx];
    __syncthreads();
    #pragma unroll
    for (int rr = 0; rr < 4; rr++) {
        float v = t[tx][ty + 8 * rr];
        unsigned short h, l; bsplit(v, h, l);
        size_t o = (size_t)(bx + ty + 8 * rr) * 2048 + by + tx;
        ((unsigned short*)Th)[o] = h;
        ((unsigned short*)Tl)[o] = l;
    }
}

// ---------------------------------------------------------------------------
// Row softmax (fp32 in) -> P hi/lo bf16. One block per row of 2048.
// ---------------------------------------------------------------------------
__global__ void __launch_bounds__(256)
softmax_kernel(const float* __restrict__ S, __nv_bfloat16* __restrict__ Ph,
               __nv_bfloat16* __restrict__ Pl)
{
    const float4* row = reinterpret_cast<const float4*>(S + (size_t)blockIdx.x * SEQ);
    const int tid = threadIdx.x, lane = tid & 31, wid = tid >> 5;

    float4 a = row[tid];
    float4 b = row[tid + 256];

    float m = fmaxf(fmaxf(fmaxf(a.x, a.y), fmaxf(a.z, a.w)),
                    fmaxf(fmaxf(b.x, b.y), fmaxf(b.z, b.w)));
    #pragma unroll
    for (int o = 16; o > 0; o >>= 1) m = fmaxf(m, __shfl_xor_sync(~0u, m, o));

    __shared__ float redm[8], reds[8];
    if (lane == 0) redm[wid] = m;
    __syncthreads();
    float bm = fmaxf(fmaxf(fmaxf(redm[0], redm[1]), fmaxf(redm[2], redm[3])),
                     fmaxf(fmaxf(redm[4], redm[5]), fmaxf(redm[6], redm[7])));

    a.x = expf(a.x - bm); a.y = expf(a.y - bm); a.z = expf(a.z - bm); a.w = expf(a.w - bm);
    b.x = expf(b.x - bm); b.y = expf(b.y - bm); b.z = expf(b.z - bm); b.w = expf(b.w - bm);

    float sm = a.x + a.y + a.z + a.w + b.x + b.y + b.z + b.w;
    #pragma unroll
    for (int o = 16; o > 0; o >>= 1) sm += __shfl_xor_sync(~0u, sm, o);
    if (lane == 0) reds[wid] = sm;
    __syncthreads();
    float bs = reds[0] + reds[1] + reds[2] + reds[3] + reds[4] + reds[5] + reds[6] + reds[7];
    float inv = 1.0f / bs;

    const size_t base = (size_t)blockIdx.x * SEQ;
    unsigned short* PH = (unsigned short*)Ph;
    unsigned short* PL = (unsigned short*)Pl;
    ushort4 H, L;
    bsplit(a.x * inv, H.x, L.x); bsplit(a.y * inv, H.y, L.y);
    bsplit(a.z * inv, H.z, L.z); bsplit(a.w * inv, H.w, L.w);
    *reinterpret_cast<ushort4*>(PH + base + tid * 4) = H;
    *reinterpret_cast<ushort4*>(PL + base + tid * 4) = L;
    bsplit(b.x * inv, H.x, L.x); bsplit(b.y * inv, H.y, L.y);
    bsplit(b.z * inv, H.z, L.z); bsplit(b.w * inv, H.w, L.w);
    *reinterpret_cast<ushort4*>(PH + base + (tid + 256) * 4) = H;
    *reinterpret_cast<ushort4*>(PL + base + (tid + 256) * 4) = L;
}

// ---------------------------------------------------------------------------
// Launch
// ---------------------------------------------------------------------------
extern "C" void kernel_launch(void* const* d_in, const int* in_sizes, int n_in,
                              void* d_out, int out_size)
{
    (void)in_sizes; (void)n_in; (void)out_size;
    const float* x  = (const float*)d_in[0];
    const float* Wq = (const float*)d_in[1];
    const float* Wk = (const float*)d_in[2];
    const float* Wv = (const float*)d_in[3];
    const float* Wo = (const float*)d_in[4];
    float* out = (float*)d_out;

    __nv_bfloat16 *xh, *xl, *Wth, *Wtl, *Qh, *Ql, *Kh, *Kl, *Vth, *Vtl, *Ph, *Pl, *Oh, *Ol;
    float* S;
    cudaGetSymbolAddress((void**)&xh,  g_xh);  cudaGetSymbolAddress((void**)&xl,  g_xl);
    cudaGetSymbolAddress((void**)&Wth, g_Wth); cudaGetSymbolAddress((void**)&Wtl, g_Wtl);
    cudaGetSymbolAddress((void**)&Qh,  g_Qh);  cudaGetSymbolAddress((void**)&Ql,  g_Ql);
    cudaGetSymbolAddress((void**)&Kh,  g_Kh);  cudaGetSymbolAddress((void**)&Kl,  g_Kl);
    cudaGetSymbolAddress((void**)&Vth, g_Vth); cudaGetSymbolAddress((void**)&Vtl, g_Vtl);
    cudaGetSymbolAddress((void**)&S,   g_S);
    cudaGetSymbolAddress((void**)&Ph,  g_Ph);  cudaGetSymbolAddress((void**)&Pl,  g_Pl);
    cudaGetSymbolAddress((void**)&Oh,  g_Oh);  cudaGetSymbolAddress((void**)&Ol,  g_Ol);

    cudaFuncSetAttribute(gemm_mma<0>, cudaFuncAttributeMaxDynamicSharedMemorySize, SMEM_SZ);
    cudaFuncSetAttribute(gemm_mma<1>, cudaFuncAttributeMaxDynamicSharedMemorySize, SMEM_SZ);
    cudaFuncSetAttribute(gemm_mma<2>, cudaFuncAttributeMaxDynamicSharedMemorySize, SMEM_SZ);

    const float scale = 1.0f / sqrtf((float)D_MODEL);
    const long sBSS = (long)SEQ * SEQ;          // 4194304
    const long sSD  = (long)SEQ * D_MODEL;      // 4194304

    // splits / transposes
    split_kernel<<<ELEMS / 1024, 256>>>(x, xh, xl);
    dim3 tg(64, 64);
    tsplit_kernel<<<tg, 256>>>(Wq, Wth + 0 * WELEMS, Wtl + 0 * WELEMS);
    tsplit_kernel<<<tg, 256>>>(Wk, Wth + 1 * WELEMS, Wtl + 1 * WELEMS);
    tsplit_kernel<<<tg, 256>>>(Wv, Wth + 2 * WELEMS, Wtl + 2 * WELEMS);
    tsplit_kernel<<<tg, 256>>>(Wo, Wth + 3 * WELEMS, Wtl + 3 * WELEMS);

    const dim3 gProj(D_MODEL / 128, MROWS / 128, 1);   // (16, 32)
    const dim3 gAttn(SEQ / 128, SEQ / 128, BATCH);     // (16, 16, 2)

    // Q, K projections (split epilogue)
    gemm_mma<1><<<gProj, 256, SMEM_SZ>>>(xh, xl, Wth + 0 * WELEMS, Wtl + 0 * WELEMS,
                                         nullptr, Qh, Ql, 0, 0, 0, 1.0f);
    gemm_mma<1><<<gProj, 256, SMEM_SZ>>>(xh, xl, Wth + 1 * WELEMS, Wtl + 1 * WELEMS,
                                         nullptr, Kh, Kl, 0, 0, 0, 1.0f);
    // V projection (split + transpose epilogue -> V^T[b][d][s])
    gemm_mma<2><<<gProj, 256, SMEM_SZ>>>(xh, xl, Wth + 2 * WELEMS, Wtl + 2 * WELEMS,
                                         nullptr, Vth, Vtl, 0, 0, 0, 1.0f);
    // scores = scale * Q @ K^T  (fp32 epilogue)
    gemm_mma<0><<<gAttn, 256, SMEM_SZ>>>(Qh, Ql, Kh, Kl,
                                         S, nullptr, nullptr, sSD, sSD, sBSS, scale);
    // softmax -> P hi/lo
    softmax_kernel<<<BATCH * SEQ, 256>>>(S, Ph, Pl);
    // O = P @ V  (B operand = V^T, split epilogue)
    gemm_mma<1><<<gAttn, 256, SMEM_SZ>>>(Ph, Pl, Vth, Vtl,
                                         nullptr, Oh, Ol, sBSS, sSD, sSD, 1.0f);
    // out = O @ W_o  (fp32 epilogue)
    gemm_mma<0><<<gProj, 256, SMEM_SZ>>>(Oh, Ol, Wth + 3 * WELEMS, Wtl + 3 * WELEMS,
                                         out, nullptr, nullptr, 0, 0, 0, 1.0f);
}

// round 5
// speedup vs baseline: 2.0531x; 1.1301x over previous
#include <cuda_runtime.h>
#include <cuda_bf16.h>
#include <math.h>
#include <stdint.h>

#define D_MODEL 2048
#define BATCH   2
#define SEQ     2048
#define MROWS   (BATCH * SEQ)                 // 4096
#define ELEMS   ((size_t)MROWS * D_MODEL)     // 8388608
#define WELEMS  ((size_t)D_MODEL * D_MODEL)   // 4194304

// ---------------------------------------------------------------------------
// Device scratch (allocation-free contract)
// ---------------------------------------------------------------------------
__device__ __nv_bfloat16 g_xh[ELEMS],  g_xl[ELEMS];
__device__ __nv_bfloat16 g_Wth[4 * WELEMS], g_Wtl[4 * WELEMS];  // W^T hi/lo, [n][k]
__device__ __nv_bfloat16 g_Qh[ELEMS],  g_Ql[ELEMS];
__device__ __nv_bfloat16 g_Kh[ELEMS],  g_Kl[ELEMS];
__device__ __nv_bfloat16 g_Vth[ELEMS], g_Vtl[ELEMS];            // V^T: [b][d][s]
__device__ float         g_S [(size_t)BATCH * SEQ * SEQ];
__device__ __nv_bfloat16 g_Ph[(size_t)BATCH * SEQ * SEQ], g_Pl[(size_t)BATCH * SEQ * SEQ];
__device__ __nv_bfloat16 g_Oh[ELEMS],  g_Ol[ELEMS];

// ---------------------------------------------------------------------------
// Helpers
// ---------------------------------------------------------------------------
__device__ __forceinline__ uint32_t s2u(const void* p) {
    return (uint32_t)__cvta_generic_to_shared(p);
}
__device__ __forceinline__ void cp16(uint32_t dst, const void* src) {
    asm volatile("cp.async.cg.shared.global [%0], [%1], 16;\n"
                 :: "r"(dst), "l"(__cvta_generic_to_global(src)));
}
__device__ __forceinline__ void cp_commit() { asm volatile("cp.async.commit_group;"); }
template<int N> __device__ __forceinline__ void cp_wait() {
    asm volatile("cp.async.wait_group %0;" :: "n"(N));
}
__device__ __forceinline__ void ldm_x4(uint32_t* r, uint32_t addr) {
    asm volatile("ldmatrix.sync.aligned.m8n8.x4.shared.b16 {%0,%1,%2,%3}, [%4];"
                 : "=r"(r[0]), "=r"(r[1]), "=r"(r[2]), "=r"(r[3]) : "r"(addr));
}
__device__ __forceinline__ void mma_bf16(float* d, const uint32_t* a,
                                         uint32_t b0, uint32_t b1) {
    asm volatile(
        "mma.sync.aligned.m16n8k16.row.col.f32.bf16.bf16.f32 "
        "{%0,%1,%2,%3}, {%4,%5,%6,%7}, {%8,%9}, {%0,%1,%2,%3};"
        : "+f"(d[0]), "+f"(d[1]), "+f"(d[2]), "+f"(d[3])
        : "r"(a[0]), "r"(a[1]), "r"(a[2]), "r"(a[3]), "r"(b0), "r"(b1));
}
__device__ __forceinline__ void bsplit(float v, unsigned short& h, unsigned short& l) {
    __nv_bfloat16 bh = __float2bfloat16(v);
    float fh = __bfloat162float(bh);
    __nv_bfloat16 bl = __float2bfloat16(v - fh);
    h = *reinterpret_cast<unsigned short*>(&bh);
    l = *reinterpret_cast<unsigned short*>(&bl);
}

// ---------------------------------------------------------------------------
// mma.sync GEMM: D[m,n] = sum_k (Ah+Al)[m,k] * (Bh+Bl)[n,k]  (3-term split)
// A: [M,2048] row-major bf16 ; B: [N,2048] row-major bf16 (K-major "B^T").
// CTA tile 128x128, 16 warps (warp tile 32x32, 4x4 grid -> 4 warps/SMSP),
// K-chunk 32, 4-stage cp.async.  Smem rows padded to 80 B: conflict-free.
// EPI: 0 = fp32*alpha -> Cf ; 1 = bf16 hi/lo split -> Ch/Cl ;
//      2 = split + per-batch transpose (V^T): Ch/Cl[b][n][s], b = m>>11.
// Global row stride is 2048 elements for every operand in this problem.
// ---------------------------------------------------------------------------
#define KC      32
#define STAGES  4
#define ROWB    80
#define TILEB   (128 * ROWB)      // 10240 per operand array
#define STG     (4 * TILEB)       // 40960 per stage (Ah, Al, Bh, Bl)
#define NCH     (2048 / KC)       // 64
#define SMEM_SZ (STAGES * STG)    // 163840
#define GTHR    512

template<int EPI>
__global__ void __launch_bounds__(GTHR, 1)
gemm_mma(const __nv_bfloat16* __restrict__ Ah, const __nv_bfloat16* __restrict__ Al,
         const __nv_bfloat16* __restrict__ Bh, const __nv_bfloat16* __restrict__ Bl,
         float* __restrict__ Cf, __nv_bfloat16* __restrict__ Ch,
         __nv_bfloat16* __restrict__ Cl,
         long sA, long sB, long sC, float alpha)
{
    extern __shared__ char smem[];
    const uint32_t sb = s2u(smem);
    const int tid  = threadIdx.x;
    const int warp = tid >> 5;
    const int lane = tid & 31;
    const int wm   = warp & 3;           // 0..3  (M)
    const int wn   = warp >> 2;          // 0..3  (N)

    const long rowA0 = (long)blockIdx.y * 128;
    const long colB0 = (long)blockIdx.x * 128;
    const __nv_bfloat16* A0h = Ah + (long)blockIdx.z * sA;
    const __nv_bfloat16* A0l = Al + (long)blockIdx.z * sA;
    const __nv_bfloat16* B0h = Bh + (long)blockIdx.z * sB;
    const __nv_bfloat16* B0l = Bl + (long)blockIdx.z * sB;

    // loads: 512 threads, each does 1 cp16 per array (row = tid>>2, seg = tid&3)
    const int lr = tid >> 2;
    const int lsg = tid & 3;
    auto load_chunk = [&](int chunk, int stage) {
        const int k0 = chunk * KC;
        const uint32_t base = sb + (uint32_t)stage * STG;
        const uint32_t d = base + (uint32_t)(lr * ROWB + lsg * 16);
        const long gA = (rowA0 + lr) * 2048 + k0 + lsg * 8;
        const long gB = (colB0 + lr) * 2048 + k0 + lsg * 8;
        cp16(d,             A0h + gA);
        cp16(d + TILEB,     A0l + gA);
        cp16(d + 2 * TILEB, B0h + gB);
        cp16(d + 3 * TILEB, B0l + gB);
    };

    // ldmatrix per-thread address pieces
    const int fr  = lane & 15;           // row within 16-row tile pair
    const int fc  = (lane >> 4) << 4;    // byte col 0 or 16
    const uint32_t aoff = (uint32_t)((wm * 32 + fr) * ROWB + fc);
    const uint32_t boff = (uint32_t)((wn * 32 + fr) * ROWB + fc);

    float acc[2][4][4];
    #pragma unroll
    for (int i = 0; i < 2; i++)
        #pragma unroll
        for (int j = 0; j < 4; j++)
            #pragma unroll
            for (int c = 0; c < 4; c++)
                acc[i][j][c] = 0.0f;

    // prologue
    load_chunk(0, 0); cp_commit();
    load_chunk(1, 1); cp_commit();
    load_chunk(2, 2); cp_commit();

    for (int i = 0; i < NCH; i++) {
        if (i < NCH - 2)       cp_wait<2>();
        else if (i == NCH - 2) cp_wait<1>();
        else                   cp_wait<0>();
        __syncthreads();

        if (i + STAGES - 1 < NCH) {
            load_chunk(i + STAGES - 1, (i + STAGES - 1) & (STAGES - 1));
            cp_commit();
        }

        const uint32_t base = sb + (uint32_t)(i & (STAGES - 1)) * STG;
        #pragma unroll
        for (int ks = 0; ks < 2; ks++) {
            uint32_t aH[2][4], aL[2][4], bH[2][4], bL[2][4];
            #pragma unroll
            for (int mf = 0; mf < 2; mf++) {
                uint32_t ad = base + aoff + (uint32_t)(mf * 16 * ROWB + ks * 32);
                ldm_x4(aH[mf], ad);
                ldm_x4(aL[mf], ad + TILEB);
            }
            #pragma unroll
            for (int nf = 0; nf < 2; nf++) {
                uint32_t bd = base + 2 * TILEB + boff
                            + (uint32_t)(nf * 16 * ROWB + ks * 32);
                ldm_x4(bH[nf], bd);
                ldm_x4(bL[nf], bd + TILEB);
            }
            #pragma unroll
            for (int mf = 0; mf < 2; mf++)
                #pragma unroll
                for (int j = 0; j < 4; j++) {
                    const int nf = j >> 1, o = j & 1;
                    mma_bf16(acc[mf][j], aH[mf], bH[nf][o], bH[nf][o + 2]);
                    mma_bf16(acc[mf][j], aH[mf], bL[nf][o], bL[nf][o + 2]);
                    mma_bf16(acc[mf][j], aL[mf], bH[nf][o], bH[nf][o + 2]);
                }
        }
    }
    __syncthreads();

    // ------------------------------- epilogue -------------------------------
    const int er = lane >> 2;            // 0..7
    const int ec = (lane & 3) << 1;      // 0,2,4,6
    #pragma unroll
    for (int mf = 0; mf < 2; mf++) {
        const long m0 = rowA0 + wm * 32 + mf * 16 + er;   // and +8
        #pragma unroll
        for (int j = 0; j < 4; j++) {
            const long n = colB0 + wn * 32 + j * 8 + ec;
            if (EPI == 0) {
                float* C = Cf + (long)blockIdx.z * sC;
                float2 v0 = make_float2(alpha * acc[mf][j][0], alpha * acc[mf][j][1]);
                float2 v1 = make_float2(alpha * acc[mf][j][2], alpha * acc[mf][j][3]);
                *reinterpret_cast<float2*>(C + m0 * 2048 + n)       = v0;
                *reinterpret_cast<float2*>(C + (m0 + 8) * 2048 + n) = v1;
            } else if (EPI == 1) {
                unsigned short* CH = (unsigned short*)Ch + (long)blockIdx.z * sC;
                unsigned short* CL = (unsigned short*)Cl + (long)blockIdx.z * sC;
                ushort2 H, L;
                bsplit(acc[mf][j][0], H.x, L.x);
                bsplit(acc[mf][j][1], H.y, L.y);
                *reinterpret_cast<ushort2*>(CH + m0 * 2048 + n) = H;
                *reinterpret_cast<ushort2*>(CL + m0 * 2048 + n) = L;
                bsplit(acc[mf][j][2], H.x, L.x);
                bsplit(acc[mf][j][3], H.y, L.y);
                *reinterpret_cast<ushort2*>(CH + (m0 + 8) * 2048 + n) = H;
                *reinterpret_cast<ushort2*>(CL + (m0 + 8) * 2048 + n) = L;
            } else {
                // V^T scatter: element (m, n) -> [b][n][s], b = m>>11, s = m&2047
                unsigned short* CH = (unsigned short*)Ch;
                unsigned short* CL = (unsigned short*)Cl;
                #pragma unroll
                for (int c = 0; c < 4; c++) {
                    long m = m0 + (c >> 1) * 8;
                    long nn = n + (c & 1);
                    long b = m >> 11, sl = m & 2047;
                    unsigned short h, l;
                    bsplit(acc[mf][j][c], h, l);
                    CH[b * 4194304 + nn * 2048 + sl] = h;
                    CL[b * 4194304 + nn * 2048 + sl] = l;
                }
            }
        }
    }
}

// ---------------------------------------------------------------------------
// x -> hi/lo bf16 split (elementwise, float4)
// ---------------------------------------------------------------------------
__global__ void __launch_bounds__(256)
split_kernel(const float* __restrict__ in, __nv_bfloat16* __restrict__ hi,
             __nv_bfloat16* __restrict__ lo)
{
    size_t i = ((size_t)blockIdx.x * 256 + threadIdx.x) * 4;
    float4 v = *reinterpret_cast<const float4*>(in + i);
    ushort4 H, L;
    bsplit(v.x, H.x, L.x); bsplit(v.y, H.y, L.y);
    bsplit(v.z, H.z, L.z); bsplit(v.w, H.w, L.w);
    *reinterpret_cast<ushort4*>((unsigned short*)hi + i) = H;
    *reinterpret_cast<ushort4*>((unsigned short*)lo + i) = L;
}

// ---------------------------------------------------------------------------
// W [k][n] fp32 -> W^T [n][k] bf16 hi/lo (tiled transpose)
// ---------------------------------------------------------------------------
__global__ void __launch_bounds__(256)
tsplit_kernel(const float* __restrict__ W, __nv_bfloat16* __restrict__ Th,
              __nv_bfloat16* __restrict__ Tl)
{
    __shared__ float t[32][33];
    const int bx = blockIdx.x * 32, by = blockIdx.y * 32;
    const int tx = threadIdx.x & 31, ty = threadIdx.x >> 5;   // 32 x 8
    #pragma unroll
    for (int rr = 0; rr < 4; rr++)
        t[ty + 8 * rr][tx] = W[(size_t)(by + ty + 8 * rr) * 2048 + bx + tx];
    __syncthreads();
    #pragma unroll
    for (int rr = 0; rr < 4; rr++) {
        float v = t[tx][ty + 8 * rr];
        unsigned short h, l; bsplit(v, h, l);
        size_t o = (size_t)(bx + ty + 8 * rr) * 2048 + by + tx;
        ((unsigned short*)Th)[o] = h;
        ((unsigned short*)Tl)[o] = l;
    }
}

// ---------------------------------------------------------------------------
// Row softmax (fp32 in) -> P hi/lo bf16. One block per row of 2048.
// ---------------------------------------------------------------------------
__global__ void __launch_bounds__(256)
softmax_kernel(const float* __restrict__ S, __nv_bfloat16* __restrict__ Ph,
               __nv_bfloat16* __restrict__ Pl)
{
    const float4* row = reinterpret_cast<const float4*>(S + (size_t)blockIdx.x * SEQ);
    const int tid = threadIdx.x, lane = tid & 31, wid = tid >> 5;

    float4 a = row[tid];
    float4 b = row[tid + 256];

    float m = fmaxf(fmaxf(fmaxf(a.x, a.y), fmaxf(a.z, a.w)),
                    fmaxf(fmaxf(b.x, b.y), fmaxf(b.z, b.w)));
    #pragma unroll
    for (int o = 16; o > 0; o >>= 1) m = fmaxf(m, __shfl_xor_sync(~0u, m, o));

    __shared__ float redm[8], reds[8];
    if (lane == 0) redm[wid] = m;
    __syncthreads();
    float bm = fmaxf(fmaxf(fmaxf(redm[0], redm[1]), fmaxf(redm[2], redm[3])),
                     fmaxf(fmaxf(redm[4], redm[5]), fmaxf(redm[6], redm[7])));

    a.x = expf(a.x - bm); a.y = expf(a.y - bm); a.z = expf(a.z - bm); a.w = expf(a.w - bm);
    b.x = expf(b.x - bm); b.y = expf(b.y - bm); b.z = expf(b.z - bm); b.w = expf(b.w - bm);

    float sm = a.x + a.y + a.z + a.w + b.x + b.y + b.z + b.w;
    #pragma unroll
    for (int o = 16; o > 0; o >>= 1) sm += __shfl_xor_sync(~0u, sm, o);
    if (lane == 0) reds[wid] = sm;
    __syncthreads();
    float bs = reds[0] + reds[1] + reds[2] + reds[3] + reds[4] + reds[5] + reds[6] + reds[7];
    float inv = 1.0f / bs;

    const size_t base = (size_t)blockIdx.x * SEQ;
    unsigned short* PH = (unsigned short*)Ph;
    unsigned short* PL = (unsigned short*)Pl;
    ushort4 H, L;
    bsplit(a.x * inv, H.x, L.x); bsplit(a.y * inv, H.y, L.y);
    bsplit(a.z * inv, H.z, L.z); bsplit(a.w * inv, H.w, L.w);
    *reinterpret_cast<ushort4*>(PH + base + tid * 4) = H;
    *reinterpret_cast<ushort4*>(PL + base + tid * 4) = L;
    bsplit(b.x * inv, H.x, L.x); bsplit(b.y * inv, H.y, L.y);
    bsplit(b.z * inv, H.z, L.z); bsplit(b.w * inv, H.w, L.w);
    *reinterpret_cast<ushort4*>(PH + base + (tid + 256) * 4) = H;
    *reinterpret_cast<ushort4*>(PL + base + (tid + 256) * 4) = L;
}

// ---------------------------------------------------------------------------
// Launch
// ---------------------------------------------------------------------------
extern "C" void kernel_launch(void* const* d_in, const int* in_sizes, int n_in,
                              void* d_out, int out_size)
{
    (void)in_sizes; (void)n_in; (void)out_size;
    const float* x  = (const float*)d_in[0];
    const float* Wq = (const float*)d_in[1];
    const float* Wk = (const float*)d_in[2];
    const float* Wv = (const float*)d_in[3];
    const float* Wo = (const float*)d_in[4];
    float* out = (float*)d_out;

    __nv_bfloat16 *xh, *xl, *Wth, *Wtl, *Qh, *Ql, *Kh, *Kl, *Vth, *Vtl, *Ph, *Pl, *Oh, *Ol;
    float* S;
    cudaGetSymbolAddress((void**)&xh,  g_xh);  cudaGetSymbolAddress((void**)&xl,  g_xl);
    cudaGetSymbolAddress((void**)&Wth, g_Wth); cudaGetSymbolAddress((void**)&Wtl, g_Wtl);
    cudaGetSymbolAddress((void**)&Qh,  g_Qh);  cudaGetSymbolAddress((void**)&Ql,  g_Ql);
    cudaGetSymbolAddress((void**)&Kh,  g_Kh);  cudaGetSymbolAddress((void**)&Kl,  g_Kl);
    cudaGetSymbolAddress((void**)&Vth, g_Vth); cudaGetSymbolAddress((void**)&Vtl, g_Vtl);
    cudaGetSymbolAddress((void**)&S,   g_S);
    cudaGetSymbolAddress((void**)&Ph,  g_Ph);  cudaGetSymbolAddress((void**)&Pl,  g_Pl);
    cudaGetSymbolAddress((void**)&Oh,  g_Oh);  cudaGetSymbolAddress((void**)&Ol,  g_Ol);

    cudaFuncSetAttribute(gemm_mma<0>, cudaFuncAttributeMaxDynamicSharedMemorySize, SMEM_SZ);
    cudaFuncSetAttribute(gemm_mma<1>, cudaFuncAttributeMaxDynamicSharedMemorySize, SMEM_SZ);
    cudaFuncSetAttribute(gemm_mma<2>, cudaFuncAttributeMaxDynamicSharedMemorySize, SMEM_SZ);

    const float scale = 1.0f / sqrtf((float)D_MODEL);
    const long sBSS = (long)SEQ * SEQ;          // 4194304
    const long sSD  = (long)SEQ * D_MODEL;      // 4194304

    // splits / transposes
    split_kernel<<<ELEMS / 1024, 256>>>(x, xh, xl);
    dim3 tg(64, 64);
    tsplit_kernel<<<tg, 256>>>(Wq, Wth + 0 * WELEMS, Wtl + 0 * WELEMS);
    tsplit_kernel<<<tg, 256>>>(Wk, Wth + 1 * WELEMS, Wtl + 1 * WELEMS);
    tsplit_kernel<<<tg, 256>>>(Wv, Wth + 2 * WELEMS, Wtl + 2 * WELEMS);
    tsplit_kernel<<<tg, 256>>>(Wo, Wth + 3 * WELEMS, Wtl + 3 * WELEMS);

    const dim3 gProj(D_MODEL / 128, MROWS / 128, 1);   // (16, 32)
    const dim3 gAttn(SEQ / 128, SEQ / 128, BATCH);     // (16, 16, 2)

    // Q, K projections (split epilogue)
    gemm_mma<1><<<gProj, GTHR, SMEM_SZ>>>(xh, xl, Wth + 0 * WELEMS, Wtl + 0 * WELEMS,
                                          nullptr, Qh, Ql, 0, 0, 0, 1.0f);
    gemm_mma<1><<<gProj, GTHR, SMEM_SZ>>>(xh, xl, Wth + 1 * WELEMS, Wtl + 1 * WELEMS,
                                          nullptr, Kh, Kl, 0, 0, 0, 1.0f);
    // V projection (split + transpose epilogue -> V^T[b][d][s])
    gemm_mma<2><<<gProj, GTHR, SMEM_SZ>>>(xh, xl, Wth + 2 * WELEMS, Wtl + 2 * WELEMS,
                                          nullptr, Vth, Vtl, 0, 0, 0, 1.0f);
    // scores = scale * Q @ K^T  (fp32 epilogue)
    gemm_mma<0><<<gAttn, GTHR, SMEM_SZ>>>(Qh, Ql, Kh, Kl,
                                          S, nullptr, nullptr, sSD, sSD, sBSS, scale);
    // softmax -> P hi/lo
    softmax_kernel<<<BATCH * SEQ, 256>>>(S, Ph, Pl);
    // O = P @ V  (B operand = V^T, split epilogue)
    gemm_mma<1><<<gAttn, GTHR, SMEM_SZ>>>(Ph, Pl, Vth, Vtl,
                                          nullptr, Oh, Ol, sBSS, sSD, sSD, 1.0f);
    // out = O @ W_o  (fp32 epilogue)
    gemm_mma<0><<<gProj, GTHR, SMEM_SZ>>>(Oh, Ol, Wth + 3 * WELEMS, Wtl + 3 * WELEMS,
                                          out, nullptr, nullptr, 0, 0, 0, 1.0f);
}

// round 6
// speedup vs baseline: 2.8964x; 1.4107x over previous
#include <cuda_runtime.h>
#include <cuda_fp16.h>
#include <math.h>
#include <stdint.h>

#define D_MODEL 2048
#define BATCH   2
#define SEQ     2048
#define MROWS   (BATCH * SEQ)                 // 4096
#define ELEMS   ((size_t)MROWS * D_MODEL)     // 8388608
#define WELEMS  ((size_t)D_MODEL * D_MODEL)   // 4194304

// ---------------------------------------------------------------------------
// Device scratch (allocation-free contract)
// ---------------------------------------------------------------------------
__device__ __half g_xh[ELEMS],  g_xl[ELEMS];        // x hi/lo (A-side pair)
__device__ __half g_Wt[4 * WELEMS];                 // W^T single fp16, [n][k]
__device__ __half g_Qh[ELEMS],  g_Ql[ELEMS];        // Q pair (A-side of scores)
__device__ __half g_Ks[ELEMS];                      // K single (B-side of scores)
__device__ __half g_Vt[ELEMS];                      // V^T single: [b][d][s]
__device__ float  g_S [(size_t)BATCH * SEQ * SEQ];
__device__ __half g_Ph[(size_t)BATCH * SEQ * SEQ], g_Pl[(size_t)BATCH * SEQ * SEQ];
__device__ __half g_Oh[ELEMS],  g_Ol[ELEMS];

// ---------------------------------------------------------------------------
// Helpers
// ---------------------------------------------------------------------------
__device__ __forceinline__ uint32_t s2u(const void* p) {
    return (uint32_t)__cvta_generic_to_shared(p);
}
__device__ __forceinline__ void cp16(uint32_t dst, const void* src) {
    asm volatile("cp.async.cg.shared.global [%0], [%1], 16;\n"
                 :: "r"(dst), "l"(__cvta_generic_to_global(src)));
}
__device__ __forceinline__ void cp_commit() { asm volatile("cp.async.commit_group;"); }
template<int N> __device__ __forceinline__ void cp_wait() {
    asm volatile("cp.async.wait_group %0;" :: "n"(N));
}
__device__ __forceinline__ void ldm_x4(uint32_t* r, uint32_t addr) {
    asm volatile("ldmatrix.sync.aligned.m8n8.x4.shared.b16 {%0,%1,%2,%3}, [%4];"
                 : "=r"(r[0]), "=r"(r[1]), "=r"(r[2]), "=r"(r[3]) : "r"(addr));
}
__device__ __forceinline__ void mma_f16(float* d, const uint32_t* a,
                                        uint32_t b0, uint32_t b1) {
    asm volatile(
        "mma.sync.aligned.m16n8k16.row.col.f32.f16.f16.f32 "
        "{%0,%1,%2,%3}, {%4,%5,%6,%7}, {%8,%9}, {%0,%1,%2,%3};"
        : "+f"(d[0]), "+f"(d[1]), "+f"(d[2]), "+f"(d[3])
        : "r"(a[0]), "r"(a[1]), "r"(a[2]), "r"(a[3]), "r"(b0), "r"(b1));
}
__device__ __forceinline__ void hsplit(float v, unsigned short& h, unsigned short& l) {
    __half hh = __float2half_rn(v);
    float fh = __half2float(hh);
    __half hl = __float2half_rn(v - fh);
    h = *reinterpret_cast<unsigned short*>(&hh);
    l = *reinterpret_cast<unsigned short*>(&hl);
}
__device__ __forceinline__ unsigned short h1(float v) {
    __half hh = __float2half_rn(v);
    return *reinterpret_cast<unsigned short*>(&hh);
}

// ---------------------------------------------------------------------------
// mma.sync GEMM: D[m,n] = sum_k (Ah+Al)[m,k] * B[n,k]   (one-sided fp16 split)
// A: [M,2048] fp16 pair ; B: [N,2048] fp16 single (K-major "B^T").
// CTA tile 128x128, 16 warps (warp tile 32x32), K-chunk 32, 4-stage cp.async.
// Smem rows padded to 80 B -> conflict-free ldmatrix.
// EPI: 0 = fp32*alpha -> Cf ; 1 = fp16 hi/lo pair -> Ch/Cl ;
//      2 = fp16 single -> Ch ;
//      3 = fp16 single + per-batch transpose (V^T): Ch[b][n][s], b = m>>11.
// Global row stride is 2048 elements for every operand in this problem.
// ---------------------------------------------------------------------------
#define KC      32
#define STAGES  4
#define ROWB    80
#define TILEB   (128 * ROWB)      // 10240 per operand array
#define STG     (3 * TILEB)       // 30720 per stage (Ah, Al, B)
#define NCH     (2048 / KC)       // 64
#define SMEM_SZ (STAGES * STG)    // 122880
#define GTHR    512

template<int EPI>
__global__ void __launch_bounds__(GTHR, 1)
gemm_mma(const __half* __restrict__ Ah, const __half* __restrict__ Al,
         const __half* __restrict__ B,
         float* __restrict__ Cf, __half* __restrict__ Ch, __half* __restrict__ Cl,
         long sA, long sB, long sC, float alpha)
{
    extern __shared__ char smem[];
    const uint32_t sb = s2u(smem);
    const int tid  = threadIdx.x;
    const int warp = tid >> 5;
    const int lane = tid & 31;
    const int wm   = warp & 3;           // 0..3  (M)
    const int wn   = warp >> 2;          // 0..3  (N)

    const long rowA0 = (long)blockIdx.y * 128;
    const long colB0 = (long)blockIdx.x * 128;
    const __half* A0h = Ah + (long)blockIdx.z * sA;
    const __half* A0l = Al + (long)blockIdx.z * sA;
    const __half* B0  = B  + (long)blockIdx.z * sB;

    // loads: 512 threads, 1 cp16 per array each (row = tid>>2, seg = tid&3)
    const int lr  = tid >> 2;
    const int lsg = tid & 3;
    auto load_chunk = [&](int chunk, int stage) {
        const int k0 = chunk * KC;
        const uint32_t base = sb + (uint32_t)stage * STG;
        const uint32_t d = base + (uint32_t)(lr * ROWB + lsg * 16);
        const long gA = (rowA0 + lr) * 2048 + k0 + lsg * 8;
        const long gB = (colB0 + lr) * 2048 + k0 + lsg * 8;
        cp16(d,             A0h + gA);
        cp16(d + TILEB,     A0l + gA);
        cp16(d + 2 * TILEB, B0  + gB);
    };

    // ldmatrix per-thread address pieces
    const int fr  = lane & 15;           // row within 16-row tile pair
    const int fc  = (lane >> 4) << 4;    // byte col 0 or 16
    const uint32_t aoff = (uint32_t)((wm * 32 + fr) * ROWB + fc);
    const uint32_t boff = (uint32_t)((wn * 32 + fr) * ROWB + fc);

    float acc[2][4][4];
    #pragma unroll
    for (int i = 0; i < 2; i++)
        #pragma unroll
        for (int j = 0; j < 4; j++)
            #pragma unroll
            for (int c = 0; c < 4; c++)
                acc[i][j][c] = 0.0f;

    // prologue
    load_chunk(0, 0); cp_commit();
    load_chunk(1, 1); cp_commit();
    load_chunk(2, 2); cp_commit();

    for (int i = 0; i < NCH; i++) {
        if (i < NCH - 2)       cp_wait<2>();
        else if (i == NCH - 2) cp_wait<1>();
        else                   cp_wait<0>();
        __syncthreads();

        if (i + STAGES - 1 < NCH) {
            load_chunk(i + STAGES - 1, (i + STAGES - 1) & (STAGES - 1));
            cp_commit();
        }

        const uint32_t base = sb + (uint32_t)(i & (STAGES - 1)) * STG;
        #pragma unroll
        for (int ks = 0; ks < 2; ks++) {
            uint32_t aH[2][4], aL[2][4], bb[2][4];
            #pragma unroll
            for (int mf = 0; mf < 2; mf++) {
                uint32_t ad = base + aoff + (uint32_t)(mf * 16 * ROWB + ks * 32);
                ldm_x4(aH[mf], ad);
                ldm_x4(aL[mf], ad + TILEB);
            }
            #pragma unroll
            for (int nf = 0; nf < 2; nf++) {
                uint32_t bd = base + 2 * TILEB + boff
                            + (uint32_t)(nf * 16 * ROWB + ks * 32);
                ldm_x4(bb[nf], bd);
            }
            #pragma unroll
            for (int mf = 0; mf < 2; mf++)
                #pragma unroll
                for (int j = 0; j < 4; j++) {
                    const int nf = j >> 1, o = j & 1;
                    mma_f16(acc[mf][j], aH[mf], bb[nf][o], bb[nf][o + 2]);
                    mma_f16(acc[mf][j], aL[mf], bb[nf][o], bb[nf][o + 2]);
                }
        }
    }
    __syncthreads();

    // ------------------------------- epilogue -------------------------------
    const int er = lane >> 2;            // 0..7
    const int ec = (lane & 3) << 1;      // 0,2,4,6
    #pragma unroll
    for (int mf = 0; mf < 2; mf++) {
        const long m0 = rowA0 + wm * 32 + mf * 16 + er;   // and +8
        #pragma unroll
        for (int j = 0; j < 4; j++) {
            const long n = colB0 + wn * 32 + j * 8 + ec;
            if (EPI == 0) {
                float* C = Cf + (long)blockIdx.z * sC;
                float2 v0 = make_float2(alpha * acc[mf][j][0], alpha * acc[mf][j][1]);
                float2 v1 = make_float2(alpha * acc[mf][j][2], alpha * acc[mf][j][3]);
                *reinterpret_cast<float2*>(C + m0 * 2048 + n)       = v0;
                *reinterpret_cast<float2*>(C + (m0 + 8) * 2048 + n) = v1;
            } else if (EPI == 1) {
                unsigned short* CH = (unsigned short*)Ch + (long)blockIdx.z * sC;
                unsigned short* CL = (unsigned short*)Cl + (long)blockIdx.z * sC;
                ushort2 H, L;
                hsplit(acc[mf][j][0], H.x, L.x);
                hsplit(acc[mf][j][1], H.y, L.y);
                *reinterpret_cast<ushort2*>(CH + m0 * 2048 + n) = H;
                *reinterpret_cast<ushort2*>(CL + m0 * 2048 + n) = L;
                hsplit(acc[mf][j][2], H.x, L.x);
                hsplit(acc[mf][j][3], H.y, L.y);
                *reinterpret_cast<ushort2*>(CH + (m0 + 8) * 2048 + n) = H;
                *reinterpret_cast<ushort2*>(CL + (m0 + 8) * 2048 + n) = L;
            } else if (EPI == 2) {
                unsigned short* C = (unsigned short*)Ch + (long)blockIdx.z * sC;
                ushort2 v0 = make_ushort2(h1(acc[mf][j][0]), h1(acc[mf][j][1]));
                ushort2 v1 = make_ushort2(h1(acc[mf][j][2]), h1(acc[mf][j][3]));
                *reinterpret_cast<ushort2*>(C + m0 * 2048 + n)       = v0;
                *reinterpret_cast<ushort2*>(C + (m0 + 8) * 2048 + n) = v1;
            } else {
                // V^T scatter: element (m, n) -> [b][n][s], b = m>>11, s = m&2047
                unsigned short* C = (unsigned short*)Ch;
                #pragma unroll
                for (int c = 0; c < 4; c++) {
                    long m = m0 + (c >> 1) * 8;
                    long nn = n + (c & 1);
                    long b = m >> 11, sl = m & 2047;
                    C[b * 4194304 + nn * 2048 + sl] = h1(acc[mf][j][c]);
                }
            }
        }
    }
}

// ---------------------------------------------------------------------------
// x -> hi/lo fp16 split (elementwise, float4)
// ---------------------------------------------------------------------------
__global__ void __launch_bounds__(256)
split_kernel(const float* __restrict__ in, __half* __restrict__ hi,
             __half* __restrict__ lo)
{
    size_t i = ((size_t)blockIdx.x * 256 + threadIdx.x) * 4;
    float4 v = *reinterpret_cast<const float4*>(in + i);
    ushort4 H, L;
    hsplit(v.x, H.x, L.x); hsplit(v.y, H.y, L.y);
    hsplit(v.z, H.z, L.z); hsplit(v.w, H.w, L.w);
    *reinterpret_cast<ushort4*>((unsigned short*)hi + i) = H;
    *reinterpret_cast<ushort4*>((unsigned short*)lo + i) = L;
}

// ---------------------------------------------------------------------------
// W [k][n] fp32 -> W^T [n][k] fp16 single (tiled transpose)
// ---------------------------------------------------------------------------
__global__ void __launch_bounds__(256)
tconv_kernel(const float* __restrict__ W, __half* __restrict__ T)
{
    __shared__ float t[32][33];
    const int bx = blockIdx.x * 32, by = blockIdx.y * 32;
    const int tx = threadIdx.x & 31, ty = threadIdx.x >> 5;   // 32 x 8
    #pragma unroll
    for (int rr = 0; rr < 4; rr++)
        t[ty + 8 * rr][tx] = W[(size_t)(by + ty + 8 * rr) * 2048 + bx + tx];
    __syncthreads();
    #pragma unroll
    for (int rr = 0; rr < 4; rr++) {
        size_t o = (size_t)(bx + ty + 8 * rr) * 2048 + by + tx;
        ((unsigned short*)T)[o] = h1(t[tx][ty + 8 * rr]);
    }
}

// ---------------------------------------------------------------------------
// Row softmax (fp32 in) -> P hi/lo fp16. One block per row of 2048.
// ---------------------------------------------------------------------------
__global__ void __launch_bounds__(256)
softmax_kernel(const float* __restrict__ S, __half* __restrict__ Ph,
               __half* __restrict__ Pl)
{
    const float4* row = reinterpret_cast<const float4*>(S + (size_t)blockIdx.x * SEQ);
    const int tid = threadIdx.x, lane = tid & 31, wid = tid >> 5;

    float4 a = row[tid];
    float4 b = row[tid + 256];

    float m = fmaxf(fmaxf(fmaxf(a.x, a.y), fmaxf(a.z, a.w)),
                    fmaxf(fmaxf(b.x, b.y), fmaxf(b.z, b.w)));
    #pragma unroll
    for (int o = 16; o > 0; o >>= 1) m = fmaxf(m, __shfl_xor_sync(~0u, m, o));

    __shared__ float redm[8], reds[8];
    if (lane == 0) redm[wid] = m;
    __syncthreads();
    float bm = fmaxf(fmaxf(fmaxf(redm[0], redm[1]), fmaxf(redm[2], redm[3])),
                     fmaxf(fmaxf(redm[4], redm[5]), fmaxf(redm[6], redm[7])));

    a.x = expf(a.x - bm); a.y = expf(a.y - bm); a.z = expf(a.z - bm); a.w = expf(a.w - bm);
    b.x = expf(b.x - bm); b.y = expf(b.y - bm); b.z = expf(b.z - bm); b.w = expf(b.w - bm);

    float sm = a.x + a.y + a.z + a.w + b.x + b.y + b.z + b.w;
    #pragma unroll
    for (int o = 16; o > 0; o >>= 1) sm += __shfl_xor_sync(~0u, sm, o);
    if (lane == 0) reds[wid] = sm;
    __syncthreads();
    float bs = reds[0] + reds[1] + reds[2] + reds[3] + reds[4] + reds[5] + reds[6] + reds[7];
    float inv = 1.0f / bs;

    const size_t base = (size_t)blockIdx.x * SEQ;
    unsigned short* PH = (unsigned short*)Ph;
    unsigned short* PL = (unsigned short*)Pl;
    ushort4 H, L;
    hsplit(a.x * inv, H.x, L.x); hsplit(a.y * inv, H.y, L.y);
    hsplit(a.z * inv, H.z, L.z); hsplit(a.w * inv, H.w, L.w);
    *reinterpret_cast<ushort4*>(PH + base + tid * 4) = H;
    *reinterpret_cast<ushort4*>(PL + base + tid * 4) = L;
    hsplit(b.x * inv, H.x, L.x); hsplit(b.y * inv, H.y, L.y);
    hsplit(b.z * inv, H.z, L.z); hsplit(b.w * inv, H.w, L.w);
    *reinterpret_cast<ushort4*>(PH + base + (tid + 256) * 4) = H;
    *reinterpret_cast<ushort4*>(PL + base + (tid + 256) * 4) = L;
}

// ---------------------------------------------------------------------------
// Launch
// ---------------------------------------------------------------------------
extern "C" void kernel_launch(void* const* d_in, const int* in_sizes, int n_in,
                              void* d_out, int out_size)
{
    (void)in_sizes; (void)n_in; (void)out_size;
    const float* x  = (const float*)d_in[0];
    const float* Wq = (const float*)d_in[1];
    const float* Wk = (const float*)d_in[2];
    const float* Wv = (const float*)d_in[3];
    const float* Wo = (const float*)d_in[4];
    float* out = (float*)d_out;

    __half *xh, *xl, *Wt, *Qh, *Ql, *Ks, *Vt, *Ph, *Pl, *Oh, *Ol;
    float* S;
    cudaGetSymbolAddress((void**)&xh, g_xh);  cudaGetSymbolAddress((void**)&xl, g_xl);
    cudaGetSymbolAddress((void**)&Wt, g_Wt);
    cudaGetSymbolAddress((void**)&Qh, g_Qh);  cudaGetSymbolAddress((void**)&Ql, g_Ql);
    cudaGetSymbolAddress((void**)&Ks, g_Ks);
    cudaGetSymbolAddress((void**)&Vt, g_Vt);
    cudaGetSymbolAddress((void**)&S,  g_S);
    cudaGetSymbolAddress((void**)&Ph, g_Ph);  cudaGetSymbolAddress((void**)&Pl, g_Pl);
    cudaGetSymbolAddress((void**)&Oh, g_Oh);  cudaGetSymbolAddress((void**)&Ol, g_Ol);

    cudaFuncSetAttribute(gemm_mma<0>, cudaFuncAttributeMaxDynamicSharedMemorySize, SMEM_SZ);
    cudaFuncSetAttribute(gemm_mma<1>, cudaFuncAttributeMaxDynamicSharedMemorySize, SMEM_SZ);
    cudaFuncSetAttribute(gemm_mma<2>, cudaFuncAttributeMaxDynamicSharedMemorySize, SMEM_SZ);
    cudaFuncSetAttribute(gemm_mma<3>, cudaFuncAttributeMaxDynamicSharedMemorySize, SMEM_SZ);

    const float scale = 1.0f / sqrtf((float)D_MODEL);
    const long sBSS = (long)SEQ * SEQ;          // 4194304
    const long sSD  = (long)SEQ * D_MODEL;      // 4194304

    // splits / transposes
    split_kernel<<<ELEMS / 1024, 256>>>(x, xh, xl);
    dim3 tg(64, 64);
    tconv_kernel<<<tg, 256>>>(Wq, Wt + 0 * WELEMS);
    tconv_kernel<<<tg, 256>>>(Wk, Wt + 1 * WELEMS);
    tconv_kernel<<<tg, 256>>>(Wv, Wt + 2 * WELEMS);
    tconv_kernel<<<tg, 256>>>(Wo, Wt + 3 * WELEMS);

    const dim3 gProj(D_MODEL / 128, MROWS / 128, 1);   // (16, 32)
    const dim3 gAttn(SEQ / 128, SEQ / 128, BATCH);     // (16, 16, 2)

    // Q projection (pair epilogue: Q is A-side of scores)
    gemm_mma<1><<<gProj, GTHR, SMEM_SZ>>>(xh, xl, Wt + 0 * WELEMS,
                                          nullptr, Qh, Ql, 0, 0, 0, 1.0f);
    // K projection (single epilogue: K is B-side of scores)
    gemm_mma<2><<<gProj, GTHR, SMEM_SZ>>>(xh, xl, Wt + 1 * WELEMS,
                                          nullptr, Ks, nullptr, 0, 0, 0, 1.0f);
    // V projection (single + transpose epilogue -> V^T[b][d][s])
    gemm_mma<3><<<gProj, GTHR, SMEM_SZ>>>(xh, xl, Wt + 2 * WELEMS,
                                          nullptr, Vt, nullptr, 0, 0, 0, 1.0f);
    // scores = scale * Q @ K^T  (fp32 epilogue)
    gemm_mma<0><<<gAttn, GTHR, SMEM_SZ>>>(Qh, Ql, Ks,
                                          S, nullptr, nullptr, sSD, sSD, sBSS, scale);
    // softmax -> P hi/lo
    softmax_kernel<<<BATCH * SEQ, 256>>>(S, Ph, Pl);
    // O = P @ V  (B operand = V^T, pair epilogue: O is A-side of out proj)
    gemm_mma<1><<<gAttn, GTHR, SMEM_SZ>>>(Ph, Pl, Vt,
                                          nullptr, Oh, Ol, sBSS, sSD, sSD, 1.0f);
    // out = O @ W_o  (fp32 epilogue)
    gemm_mma<0><<<gProj, GTHR, SMEM_SZ>>>(Oh, Ol, Wt + 3 * WELEMS,
                                          out, nullptr, nullptr, 0, 0, 0, 1.0f);
}

// round 7
// speedup vs baseline: 5.3143x; 1.8348x over previous
#include <cuda_runtime.h>
#include <cuda_fp16.h>
#include <math.h>
#include <stdint.h>

#define D_MODEL 2048
#define BATCH   2
#define SEQ     2048
#define MROWS   (BATCH * SEQ)                 // 4096
#define ELEMS   ((size_t)MROWS * D_MODEL)     // 8388608
#define WELEMS  ((size_t)D_MODEL * D_MODEL)   // 4194304

// ---------------------------------------------------------------------------
// Device scratch (allocation-free contract) — all single fp16 now
// ---------------------------------------------------------------------------
__device__ __half g_xs[ELEMS];                      // x fp16
__device__ __half g_Wt[4 * WELEMS];                 // W^T fp16, [n][k]
__device__ __half g_Qs[ELEMS];                      // Q
__device__ __half g_Ks[ELEMS];                      // K
__device__ __half g_Vt[ELEMS];                      // V^T: [b][d][s]
__device__ float  g_S [(size_t)BATCH * SEQ * SEQ];  // scores fp32
__device__ __half g_Ps[(size_t)BATCH * SEQ * SEQ];  // softmax(P)
__device__ __half g_Os[ELEMS];                      // attn output

// ---------------------------------------------------------------------------
// Helpers
// ---------------------------------------------------------------------------
__device__ __forceinline__ uint32_t s2u(const void* p) {
    return (uint32_t)__cvta_generic_to_shared(p);
}
__device__ __forceinline__ void cp16(uint32_t dst, const void* src) {
    asm volatile("cp.async.cg.shared.global [%0], [%1], 16;\n"
                 :: "r"(dst), "l"(__cvta_generic_to_global(src)));
}
__device__ __forceinline__ void cp_commit() { asm volatile("cp.async.commit_group;"); }
template<int N> __device__ __forceinline__ void cp_wait() {
    asm volatile("cp.async.wait_group %0;" :: "n"(N));
}
__device__ __forceinline__ void ldm_x4(uint32_t* r, uint32_t addr) {
    asm volatile("ldmatrix.sync.aligned.m8n8.x4.shared.b16 {%0,%1,%2,%3}, [%4];"
                 : "=r"(r[0]), "=r"(r[1]), "=r"(r[2]), "=r"(r[3]) : "r"(addr));
}
__device__ __forceinline__ void mma_f16(float* d, const uint32_t* a,
                                        uint32_t b0, uint32_t b1) {
    asm volatile(
        "mma.sync.aligned.m16n8k16.row.col.f32.f16.f16.f32 "
        "{%0,%1,%2,%3}, {%4,%5,%6,%7}, {%8,%9}, {%0,%1,%2,%3};"
        : "+f"(d[0]), "+f"(d[1]), "+f"(d[2]), "+f"(d[3])
        : "r"(a[0]), "r"(a[1]), "r"(a[2]), "r"(a[3]), "r"(b0), "r"(b1));
}
__device__ __forceinline__ unsigned short h1(float v) {
    __half hh = __float2half_rn(v);
    return *reinterpret_cast<unsigned short*>(&hh);
}

// ---------------------------------------------------------------------------
// mma.sync GEMM: D[m,n] = sum_k A[m,k] * B[n,k]   (single fp16 both sides)
// A: [M,2048] fp16 ; B: [N,2048] fp16 (K-major "B^T").
// CTA tile 128x128, 16 warps (warp tile 32x32), K-chunk 32, 4-stage cp.async.
// Smem rows padded to 80 B -> conflict-free ldmatrix.
// EPI: 0 = fp32*alpha -> Cf ; 2 = fp16 -> Ch ;
//      3 = fp16 + per-batch transpose (V^T): Ch[b][n][s], b = m>>11.
// Global row stride is 2048 elements for every operand in this problem.
// ---------------------------------------------------------------------------
#define KC      32
#define STAGES  4
#define ROWB    80
#define TILEB   (128 * ROWB)      // 10240 per operand array
#define STG     (2 * TILEB)       // 20480 per stage (A, B)
#define NCH     (2048 / KC)       // 64
#define SMEM_SZ (STAGES * STG)    // 81920
#define GTHR    512

template<int EPI>
__global__ void __launch_bounds__(GTHR, 1)
gemm_mma(const __half* __restrict__ A, const __half* __restrict__ B,
         float* __restrict__ Cf, __half* __restrict__ Ch,
         long sA, long sB, long sC, float alpha)
{
    extern __shared__ char smem[];
    const uint32_t sb = s2u(smem);
    const int tid  = threadIdx.x;
    const int warp = tid >> 5;
    const int lane = tid & 31;
    const int wm   = warp & 3;           // 0..3  (M)
    const int wn   = warp >> 2;          // 0..3  (N)

    const long rowA0 = (long)blockIdx.y * 128;
    const long colB0 = (long)blockIdx.x * 128;
    const __half* A0 = A + (long)blockIdx.z * sA;
    const __half* B0 = B + (long)blockIdx.z * sB;

    // loads: 512 threads, 1 cp16 per array each (row = tid>>2, seg = tid&3)
    const int lr  = tid >> 2;
    const int lsg = tid & 3;
    auto load_chunk = [&](int chunk, int stage) {
        const int k0 = chunk * KC;
        const uint32_t base = sb + (uint32_t)stage * STG;
        const uint32_t d = base + (uint32_t)(lr * ROWB + lsg * 16);
        cp16(d,         A0 + (rowA0 + lr) * 2048 + k0 + lsg * 8);
        cp16(d + TILEB, B0 + (colB0 + lr) * 2048 + k0 + lsg * 8);
    };

    // ldmatrix per-thread address pieces
    const int fr  = lane & 15;           // row within 16-row tile pair
    const int fc  = (lane >> 4) << 4;    // byte col 0 or 16
    const uint32_t aoff = (uint32_t)((wm * 32 + fr) * ROWB + fc);
    const uint32_t boff = (uint32_t)((wn * 32 + fr) * ROWB + fc);

    float acc[2][4][4];
    #pragma unroll
    for (int i = 0; i < 2; i++)
        #pragma unroll
        for (int j = 0; j < 4; j++)
            #pragma unroll
            for (int c = 0; c < 4; c++)
                acc[i][j][c] = 0.0f;

    // prologue
    load_chunk(0, 0); cp_commit();
    load_chunk(1, 1); cp_commit();
    load_chunk(2, 2); cp_commit();

    for (int i = 0; i < NCH; i++) {
        if (i < NCH - 2)       cp_wait<2>();
        else if (i == NCH - 2) cp_wait<1>();
        else                   cp_wait<0>();
        __syncthreads();

        if (i + STAGES - 1 < NCH) {
            load_chunk(i + STAGES - 1, (i + STAGES - 1) & (STAGES - 1));
            cp_commit();
        }

        const uint32_t base = sb + (uint32_t)(i & (STAGES - 1)) * STG;
        #pragma unroll
        for (int ks = 0; ks < 2; ks++) {
            uint32_t aa[2][4], bb[2][4];
            #pragma unroll
            for (int mf = 0; mf < 2; mf++) {
                uint32_t ad = base + aoff + (uint32_t)(mf * 16 * ROWB + ks * 32);
                ldm_x4(aa[mf], ad);
            }
            #pragma unroll
            for (int nf = 0; nf < 2; nf++) {
                uint32_t bd = base + TILEB + boff
                            + (uint32_t)(nf * 16 * ROWB + ks * 32);
                ldm_x4(bb[nf], bd);
            }
            #pragma unroll
            for (int mf = 0; mf < 2; mf++)
                #pragma unroll
                for (int j = 0; j < 4; j++) {
                    const int nf = j >> 1, o = j & 1;
                    mma_f16(acc[mf][j], aa[mf], bb[nf][o], bb[nf][o + 2]);
                }
        }
    }
    __syncthreads();

    // ------------------------------- epilogue -------------------------------
    const int er = lane >> 2;            // 0..7
    const int ec = (lane & 3) << 1;      // 0,2,4,6
    #pragma unroll
    for (int mf = 0; mf < 2; mf++) {
        const long m0 = rowA0 + wm * 32 + mf * 16 + er;   // and +8
        #pragma unroll
        for (int j = 0; j < 4; j++) {
            const long n = colB0 + wn * 32 + j * 8 + ec;
            if (EPI == 0) {
                float* C = Cf + (long)blockIdx.z * sC;
                float2 v0 = make_float2(alpha * acc[mf][j][0], alpha * acc[mf][j][1]);
                float2 v1 = make_float2(alpha * acc[mf][j][2], alpha * acc[mf][j][3]);
                *reinterpret_cast<float2*>(C + m0 * 2048 + n)       = v0;
                *reinterpret_cast<float2*>(C + (m0 + 8) * 2048 + n) = v1;
            } else if (EPI == 2) {
                unsigned short* C = (unsigned short*)Ch + (long)blockIdx.z * sC;
                ushort2 v0 = make_ushort2(h1(acc[mf][j][0]), h1(acc[mf][j][1]));
                ushort2 v1 = make_ushort2(h1(acc[mf][j][2]), h1(acc[mf][j][3]));
                *reinterpret_cast<ushort2*>(C + m0 * 2048 + n)       = v0;
                *reinterpret_cast<ushort2*>(C + (m0 + 8) * 2048 + n) = v1;
            } else {
                // V^T scatter: element (m, n) -> [b][n][s], b = m>>11, s = m&2047
                unsigned short* C = (unsigned short*)Ch;
                #pragma unroll
                for (int c = 0; c < 4; c++) {
                    long m = m0 + (c >> 1) * 8;
                    long nn = n + (c & 1);
                    long b = m >> 11, sl = m & 2047;
                    C[b * 4194304 + nn * 2048 + sl] = h1(acc[mf][j][c]);
                }
            }
        }
    }
}

// ---------------------------------------------------------------------------
// x fp32 -> fp16 (elementwise, float4)
// ---------------------------------------------------------------------------
__global__ void __launch_bounds__(256)
conv_kernel(const float* __restrict__ in, __half* __restrict__ out)
{
    size_t i = ((size_t)blockIdx.x * 256 + threadIdx.x) * 4;
    float4 v = *reinterpret_cast<const float4*>(in + i);
    ushort4 H;
    H.x = h1(v.x); H.y = h1(v.y); H.z = h1(v.z); H.w = h1(v.w);
    *reinterpret_cast<ushort4*>((unsigned short*)out + i) = H;
}

// ---------------------------------------------------------------------------
// W [k][n] fp32 -> W^T [n][k] fp16 (tiled transpose)
// ---------------------------------------------------------------------------
__global__ void __launch_bounds__(256)
tconv_kernel(const float* __restrict__ W, __half* __restrict__ T)
{
    __shared__ float t[32][33];
    const int bx = blockIdx.x * 32, by = blockIdx.y * 32;
    const int tx = threadIdx.x & 31, ty = threadIdx.x >> 5;   // 32 x 8
    #pragma unroll
    for (int rr = 0; rr < 4; rr++)
        t[ty + 8 * rr][tx] = W[(size_t)(by + ty + 8 * rr) * 2048 + bx + tx];
    __syncthreads();
    #pragma unroll
    for (int rr = 0; rr < 4; rr++) {
        size_t o = (size_t)(bx + ty + 8 * rr) * 2048 + by + tx;
        ((unsigned short*)T)[o] = h1(t[tx][ty + 8 * rr]);
    }
}

// ---------------------------------------------------------------------------
// Row softmax (fp32 in) -> P fp16. One block per row of 2048.
// ---------------------------------------------------------------------------
__global__ void __launch_bounds__(256)
softmax_kernel(const float* __restrict__ S, __half* __restrict__ P)
{
    const float4* row = reinterpret_cast<const float4*>(S + (size_t)blockIdx.x * SEQ);
    const int tid = threadIdx.x, lane = tid & 31, wid = tid >> 5;

    float4 a = row[tid];
    float4 b = row[tid + 256];

    float m = fmaxf(fmaxf(fmaxf(a.x, a.y), fmaxf(a.z, a.w)),
                    fmaxf(fmaxf(b.x, b.y), fmaxf(b.z, b.w)));
    #pragma unroll
    for (int o = 16; o > 0; o >>= 1) m = fmaxf(m, __shfl_xor_sync(~0u, m, o));

    __shared__ float redm[8], reds[8];
    if (lane == 0) redm[wid] = m;
    __syncthreads();
    float bm = fmaxf(fmaxf(fmaxf(redm[0], redm[1]), fmaxf(redm[2], redm[3])),
                     fmaxf(fmaxf(redm[4], redm[5]), fmaxf(redm[6], redm[7])));

    a.x = expf(a.x - bm); a.y = expf(a.y - bm); a.z = expf(a.z - bm); a.w = expf(a.w - bm);
    b.x = expf(b.x - bm); b.y = expf(b.y - bm); b.z = expf(b.z - bm); b.w = expf(b.w - bm);

    float sm = a.x + a.y + a.z + a.w + b.x + b.y + b.z + b.w;
    #pragma unroll
    for (int o = 16; o > 0; o >>= 1) sm += __shfl_xor_sync(~0u, sm, o);
    if (lane == 0) reds[wid] = sm;
    __syncthreads();
    float bs = reds[0] + reds[1] + reds[2] + reds[3] + reds[4] + reds[5] + reds[6] + reds[7];
    float inv = 1.0f / bs;

    const size_t base = (size_t)blockIdx.x * SEQ;
    unsigned short* PP = (unsigned short*)P;
    ushort4 H;
    H.x = h1(a.x * inv); H.y = h1(a.y * inv);
    H.z = h1(a.z * inv); H.w = h1(a.w * inv);
    *reinterpret_cast<ushort4*>(PP + base + tid * 4) = H;
    H.x = h1(b.x * inv); H.y = h1(b.y * inv);
    H.z = h1(b.z * inv); H.w = h1(b.w * inv);
    *reinterpret_cast<ushort4*>(PP + base + (tid + 256) * 4) = H;
}

// ---------------------------------------------------------------------------
// Launch
// ---------------------------------------------------------------------------
extern "C" void kernel_launch(void* const* d_in, const int* in_sizes, int n_in,
                              void* d_out, int out_size)
{
    (void)in_sizes; (void)n_in; (void)out_size;
    const float* x  = (const float*)d_in[0];
    const float* Wq = (const float*)d_in[1];
    const float* Wk = (const float*)d_in[2];
    const float* Wv = (const float*)d_in[3];
    const float* Wo = (const float*)d_in[4];
    float* out = (float*)d_out;

    __half *xs, *Wt, *Qs, *Ks, *Vt, *Ps, *Os;
    float* S;
    cudaGetSymbolAddress((void**)&xs, g_xs);
    cudaGetSymbolAddress((void**)&Wt, g_Wt);
    cudaGetSymbolAddress((void**)&Qs, g_Qs);
    cudaGetSymbolAddress((void**)&Ks, g_Ks);
    cudaGetSymbolAddress((void**)&Vt, g_Vt);
    cudaGetSymbolAddress((void**)&S,  g_S);
    cudaGetSymbolAddress((void**)&Ps, g_Ps);
    cudaGetSymbolAddress((void**)&Os, g_Os);

    cudaFuncSetAttribute(gemm_mma<0>, cudaFuncAttributeMaxDynamicSharedMemorySize, SMEM_SZ);
    cudaFuncSetAttribute(gemm_mma<2>, cudaFuncAttributeMaxDynamicSharedMemorySize, SMEM_SZ);
    cudaFuncSetAttribute(gemm_mma<3>, cudaFuncAttributeMaxDynamicSharedMemorySize, SMEM_SZ);

    const float scale = 1.0f / sqrtf((float)D_MODEL);
    const long sBSS = (long)SEQ * SEQ;          // 4194304
    const long sSD  = (long)SEQ * D_MODEL;      // 4194304

    // conversions
    conv_kernel<<<ELEMS / 1024, 256>>>(x, xs);
    dim3 tg(64, 64);
    tconv_kernel<<<tg, 256>>>(Wq, Wt + 0 * WELEMS);
    tconv_kernel<<<tg, 256>>>(Wk, Wt + 1 * WELEMS);
    tconv_kernel<<<tg, 256>>>(Wv, Wt + 2 * WELEMS);
    tconv_kernel<<<tg, 256>>>(Wo, Wt + 3 * WELEMS);

    const dim3 gProj(D_MODEL / 128, MROWS / 128, 1);   // (16, 32)
    const dim3 gAttn(SEQ / 128, SEQ / 128, BATCH);     // (16, 16, 2)

    // Q, K projections
    gemm_mma<2><<<gProj, GTHR, SMEM_SZ>>>(xs, Wt + 0 * WELEMS,
                                          nullptr, Qs, 0, 0, 0, 1.0f);
    gemm_mma<2><<<gProj, GTHR, SMEM_SZ>>>(xs, Wt + 1 * WELEMS,
                                          nullptr, Ks, 0, 0, 0, 1.0f);
    // V projection (transpose epilogue -> V^T[b][d][s])
    gemm_mma<3><<<gProj, GTHR, SMEM_SZ>>>(xs, Wt + 2 * WELEMS,
                                          nullptr, Vt, 0, 0, 0, 1.0f);
    // scores = scale * Q @ K^T  (fp32 epilogue)
    gemm_mma<0><<<gAttn, GTHR, SMEM_SZ>>>(Qs, Ks,
                                          S, nullptr, sSD, sSD, sBSS, scale);
    // softmax -> P fp16
    softmax_kernel<<<BATCH * SEQ, 256>>>(S, Ps);
    // O = P @ V  (B operand = V^T)
    gemm_mma<2><<<gAttn, GTHR, SMEM_SZ>>>(Ps, Vt,
                                          nullptr, Os, sBSS, sSD, sSD, 1.0f);
    // out = O @ W_o  (fp32 epilogue)
    gemm_mma<0><<<gProj, GTHR, SMEM_SZ>>>(Os, Wt + 3 * WELEMS,
                                          out, nullptr, 0, 0, 0, 1.0f);
}

// round 8
// speedup vs baseline: 5.5976x; 1.0533x over previous
#include <cuda_runtime.h>
#include <cuda_fp16.h>
#include <math.h>
#include <stdint.h>

#define D_MODEL 2048
#define BATCH   2
#define SEQ     2048
#define MROWS   (BATCH * SEQ)                 // 4096
#define ELEMS   ((size_t)MROWS * D_MODEL)     // 8388608
#define WELEMS  ((size_t)D_MODEL * D_MODEL)   // 4194304

// ---------------------------------------------------------------------------
// Device scratch (allocation-free contract) — all single fp16
// ---------------------------------------------------------------------------
__device__ __half g_xs[ELEMS];                      // x fp16
__device__ __half g_Wt[4 * WELEMS];                 // W^T fp16, [n][k]
__device__ __half g_Qs[ELEMS];                      // Q
__device__ __half g_Ks[ELEMS];                      // K
__device__ __half g_Vt[ELEMS];                      // V^T: [b][d][s]
__device__ float  g_S [(size_t)BATCH * SEQ * SEQ];  // scores fp32
__device__ __half g_Ps[(size_t)BATCH * SEQ * SEQ];  // softmax(P)
__device__ __half g_Os[ELEMS];                      // attn output

// ---------------------------------------------------------------------------
// Helpers
// ---------------------------------------------------------------------------
__device__ __forceinline__ uint32_t s2u(const void* p) {
    return (uint32_t)__cvta_generic_to_shared(p);
}
__device__ __forceinline__ void cp16(uint32_t dst, const void* src) {
    asm volatile("cp.async.cg.shared.global [%0], [%1], 16;\n"
                 :: "r"(dst), "l"(__cvta_generic_to_global(src)));
}
__device__ __forceinline__ void cp_commit() { asm volatile("cp.async.commit_group;"); }
template<int N> __device__ __forceinline__ void cp_wait() {
    asm volatile("cp.async.wait_group %0;" :: "n"(N));
}
__device__ __forceinline__ void ldm_x4(uint32_t* r, uint32_t addr) {
    asm volatile("ldmatrix.sync.aligned.m8n8.x4.shared.b16 {%0,%1,%2,%3}, [%4];"
                 : "=r"(r[0]), "=r"(r[1]), "=r"(r[2]), "=r"(r[3]) : "r"(addr));
}
__device__ __forceinline__ void mma_f16(float* d, const uint32_t* a,
                                        uint32_t b0, uint32_t b1) {
    asm volatile(
        "mma.sync.aligned.m16n8k16.row.col.f32.f16.f16.f32 "
        "{%0,%1,%2,%3}, {%4,%5,%6,%7}, {%8,%9}, {%0,%1,%2,%3};"
        : "+f"(d[0]), "+f"(d[1]), "+f"(d[2]), "+f"(d[3])
        : "r"(a[0]), "r"(a[1]), "r"(a[2]), "r"(a[3]), "r"(b0), "r"(b1));
}
__device__ __forceinline__ unsigned short h1(float v) {
    __half hh = __float2half_rn(v);
    return *reinterpret_cast<unsigned short*>(&hh);
}

// ---------------------------------------------------------------------------
// Tiling constants (shared by both GEMM kernels)
// ---------------------------------------------------------------------------
#define KC      32
#define STAGES  4
#define ROWB    80
#define TILEB   (128 * ROWB)      // 10240 per operand array
#define STG     (2 * TILEB)       // 20480 per stage (A, B)
#define NCH     (2048 / KC)       // 64
#define SMEM_SZ (STAGES * STG)    // 81920
#define GTHR    512

// ---------------------------------------------------------------------------
// Core mainloop: computes 128x128 tile accumulator for C = A @ B^T chunk-wise.
// A: rows rowA0.., B: rows colB0.. (both [*,2048] fp16 K-major, stride 2048).
// ---------------------------------------------------------------------------
struct MmaCtx {
    float acc[2][4][4];
};

__device__ __forceinline__ void gemm_mainloop(
    MmaCtx& ctx, uint32_t sb, int tid, int wm, int wn, int lane,
    const __half* A0, const __half* B0, long rowA0, long colB0)
{
    const int lr  = tid >> 2;
    const int lsg = tid & 3;
    auto load_chunk = [&](int chunk, int stage) {
        const int k0 = chunk * KC;
        const uint32_t base = sb + (uint32_t)stage * STG;
        const uint32_t d = base + (uint32_t)(lr * ROWB + lsg * 16);
        cp16(d,         A0 + (rowA0 + lr) * 2048 + k0 + lsg * 8);
        cp16(d + TILEB, B0 + (colB0 + lr) * 2048 + k0 + lsg * 8);
    };

    const int fr  = lane & 15;
    const int fc  = (lane >> 4) << 4;
    const uint32_t aoff = (uint32_t)((wm * 32 + fr) * ROWB + fc);
    const uint32_t boff = (uint32_t)((wn * 32 + fr) * ROWB + fc);

    #pragma unroll
    for (int i = 0; i < 2; i++)
        #pragma unroll
        for (int j = 0; j < 4; j++)
            #pragma unroll
            for (int c = 0; c < 4; c++)
                ctx.acc[i][j][c] = 0.0f;

    load_chunk(0, 0); cp_commit();
    load_chunk(1, 1); cp_commit();
    load_chunk(2, 2); cp_commit();

    for (int i = 0; i < NCH; i++) {
        if (i < NCH - 2)       cp_wait<2>();
        else if (i == NCH - 2) cp_wait<1>();
        else                   cp_wait<0>();
        __syncthreads();

        if (i + STAGES - 1 < NCH) {
            load_chunk(i + STAGES - 1, (i + STAGES - 1) & (STAGES - 1));
            cp_commit();
        }

        const uint32_t base = sb + (uint32_t)(i & (STAGES - 1)) * STG;
        #pragma unroll
        for (int ks = 0; ks < 2; ks++) {
            uint32_t aa[2][4], bb[2][4];
            #pragma unroll
            for (int mf = 0; mf < 2; mf++) {
                uint32_t ad = base + aoff + (uint32_t)(mf * 16 * ROWB + ks * 32);
                ldm_x4(aa[mf], ad);
            }
            #pragma unroll
            for (int nf = 0; nf < 2; nf++) {
                uint32_t bd = base + TILEB + boff
                            + (uint32_t)(nf * 16 * ROWB + ks * 32);
                ldm_x4(bb[nf], bd);
            }
            #pragma unroll
            for (int mf = 0; mf < 2; mf++)
                #pragma unroll
                for (int j = 0; j < 4; j++) {
                    const int nf = j >> 1, o = j & 1;
                    mma_f16(ctx.acc[mf][j], aa[mf], bb[nf][o], bb[nf][o + 2]);
                }
        }
    }
    __syncthreads();
}

// ---------------------------------------------------------------------------
// Generic GEMM kernel (EPI: 0 = fp32*alpha -> Cf ; 2 = fp16 -> Ch)
// ---------------------------------------------------------------------------
template<int EPI>
__global__ void __launch_bounds__(GTHR, 1)
gemm_mma(const __half* __restrict__ A, const __half* __restrict__ B,
         float* __restrict__ Cf, __half* __restrict__ Ch,
         long sA, long sB, long sC, float alpha)
{
    extern __shared__ char smem[];
    const uint32_t sb = s2u(smem);
    const int tid  = threadIdx.x;
    const int warp = tid >> 5;
    const int lane = tid & 31;
    const int wm   = warp & 3;
    const int wn   = warp >> 2;

    const long rowA0 = (long)blockIdx.y * 128;
    const long colB0 = (long)blockIdx.x * 128;

    MmaCtx ctx;
    gemm_mainloop(ctx, sb, tid, wm, wn, lane,
                  A + (long)blockIdx.z * sA, B + (long)blockIdx.z * sB,
                  rowA0, colB0);

    const int er = lane >> 2;
    const int ec = (lane & 3) << 1;
    #pragma unroll
    for (int mf = 0; mf < 2; mf++) {
        const long m0 = rowA0 + wm * 32 + mf * 16 + er;
        #pragma unroll
        for (int j = 0; j < 4; j++) {
            const long n = colB0 + wn * 32 + j * 8 + ec;
            if (EPI == 0) {
                float* C = Cf + (long)blockIdx.z * sC;
                float2 v0 = make_float2(alpha * ctx.acc[mf][j][0], alpha * ctx.acc[mf][j][1]);
                float2 v1 = make_float2(alpha * ctx.acc[mf][j][2], alpha * ctx.acc[mf][j][3]);
                *reinterpret_cast<float2*>(C + m0 * 2048 + n)       = v0;
                *reinterpret_cast<float2*>(C + (m0 + 8) * 2048 + n) = v1;
            } else {
                unsigned short* C = (unsigned short*)Ch + (long)blockIdx.z * sC;
                ushort2 v0 = make_ushort2(h1(ctx.acc[mf][j][0]), h1(ctx.acc[mf][j][1]));
                ushort2 v1 = make_ushort2(h1(ctx.acc[mf][j][2]), h1(ctx.acc[mf][j][3]));
                *reinterpret_cast<ushort2*>(C + m0 * 2048 + n)       = v0;
                *reinterpret_cast<ushort2*>(C + (m0 + 8) * 2048 + n) = v1;
            }
        }
    }
}

// ---------------------------------------------------------------------------
// Merged Q/K/V projection kernel: grid.z = weight index (0=Q, 1=K, 2=V).
// z=0 -> Qs, z=1 -> Ks (row-major), z=2 -> V^T scatter [b][n][s].
// One launch of 1536 CTAs instead of 3 x 512 -> better wave packing.
// ---------------------------------------------------------------------------
__global__ void __launch_bounds__(GTHR, 1)
gemm_qkv(const __half* __restrict__ xs, const __half* __restrict__ Wt,
         __half* __restrict__ Qs, __half* __restrict__ Ks,
         __half* __restrict__ Vt)
{
    extern __shared__ char smem[];
    const uint32_t sb = s2u(smem);
    const int tid  = threadIdx.x;
    const int warp = tid >> 5;
    const int lane = tid & 31;
    const int wm   = warp & 3;
    const int wn   = warp >> 2;
    const int z    = blockIdx.z;

    const long rowA0 = (long)blockIdx.y * 128;
    const long colB0 = (long)blockIdx.x * 128;

    MmaCtx ctx;
    gemm_mainloop(ctx, sb, tid, wm, wn, lane,
                  xs, Wt + (long)z * (long)WELEMS, rowA0, colB0);

    const int er = lane >> 2;
    const int ec = (lane & 3) << 1;
    if (z < 2) {
        unsigned short* C = (unsigned short*)(z == 0 ? Qs : Ks);
        #pragma unroll
        for (int mf = 0; mf < 2; mf++) {
            const long m0 = rowA0 + wm * 32 + mf * 16 + er;
            #pragma unroll
            for (int j = 0; j < 4; j++) {
                const long n = colB0 + wn * 32 + j * 8 + ec;
                ushort2 v0 = make_ushort2(h1(ctx.acc[mf][j][0]), h1(ctx.acc[mf][j][1]));
                ushort2 v1 = make_ushort2(h1(ctx.acc[mf][j][2]), h1(ctx.acc[mf][j][3]));
                *reinterpret_cast<ushort2*>(C + m0 * 2048 + n)       = v0;
                *reinterpret_cast<ushort2*>(C + (m0 + 8) * 2048 + n) = v1;
            }
        }
    } else {
        // V^T scatter: element (m, n) -> [b][n][s], b = m>>11, s = m&2047
        unsigned short* C = (unsigned short*)Vt;
        #pragma unroll
        for (int mf = 0; mf < 2; mf++) {
            const long m0 = rowA0 + wm * 32 + mf * 16 + er;
            #pragma unroll
            for (int j = 0; j < 4; j++) {
                const long n = colB0 + wn * 32 + j * 8 + ec;
                #pragma unroll
                for (int c = 0; c < 4; c++) {
                    long m = m0 + (c >> 1) * 8;
                    long nn = n + (c & 1);
                    long b = m >> 11, sl = m & 2047;
                    C[b * 4194304 + nn * 2048 + sl] = h1(ctx.acc[mf][j][c]);
                }
            }
        }
    }
}

// ---------------------------------------------------------------------------
// Merged conversion kernel:
//   blocks [0, 8192):      x fp32 -> fp16 (1024 elems per block)
//   blocks [8192, 24576):  W transposes, 32x32 tiles; weight = (bid-8192)/4096
// ---------------------------------------------------------------------------
__global__ void __launch_bounds__(256)
convall_kernel(const float* __restrict__ x,
               const float* __restrict__ Wq, const float* __restrict__ Wk,
               const float* __restrict__ Wv, const float* __restrict__ Wo,
               __half* __restrict__ xs, __half* __restrict__ Wt)
{
    const int bid = blockIdx.x;
    if (bid < 8192) {
        size_t i = ((size_t)bid * 256 + threadIdx.x) * 4;
        float4 v = *reinterpret_cast<const float4*>(x + i);
        ushort4 H;
        H.x = h1(v.x); H.y = h1(v.y); H.z = h1(v.z); H.w = h1(v.w);
        *reinterpret_cast<ushort4*>((unsigned short*)xs + i) = H;
        return;
    }
    const int t = bid - 8192;
    const int w = t >> 12;               // weight index 0..3
    const int ti = t & 4095;             // tile index within weight
    const float* W = (w == 0) ? Wq : (w == 1) ? Wk : (w == 2) ? Wv : Wo;
    __half* T = Wt + (size_t)w * WELEMS;

    __shared__ float tt[32][33];
    const int bx = (ti & 63) * 32, by = (ti >> 6) * 32;
    const int tx = threadIdx.x & 31, ty = threadIdx.x >> 5;   // 32 x 8
    #pragma unroll
    for (int rr = 0; rr < 4; rr++)
        tt[ty + 8 * rr][tx] = W[(size_t)(by + ty + 8 * rr) * 2048 + bx + tx];
    __syncthreads();
    #pragma unroll
    for (int rr = 0; rr < 4; rr++) {
        size_t o = (size_t)(bx + ty + 8 * rr) * 2048 + by + tx;
        ((unsigned short*)T)[o] = h1(tt[tx][ty + 8 * rr]);
    }
}

// ---------------------------------------------------------------------------
// Row softmax (fp32 in) -> P fp16. One block per row of 2048.
// ---------------------------------------------------------------------------
__global__ void __launch_bounds__(256)
softmax_kernel(const float* __restrict__ S, __half* __restrict__ P)
{
    const float4* row = reinterpret_cast<const float4*>(S + (size_t)blockIdx.x * SEQ);
    const int tid = threadIdx.x, lane = tid & 31, wid = tid >> 5;

    float4 a = row[tid];
    float4 b = row[tid + 256];

    float m = fmaxf(fmaxf(fmaxf(a.x, a.y), fmaxf(a.z, a.w)),
                    fmaxf(fmaxf(b.x, b.y), fmaxf(b.z, b.w)));
    #pragma unroll
    for (int o = 16; o > 0; o >>= 1) m = fmaxf(m, __shfl_xor_sync(~0u, m, o));

    __shared__ float redm[8], reds[8];
    if (lane == 0) redm[wid] = m;
    __syncthreads();
    float bm = fmaxf(fmaxf(fmaxf(redm[0], redm[1]), fmaxf(redm[2], redm[3])),
                     fmaxf(fmaxf(redm[4], redm[5]), fmaxf(redm[6], redm[7])));

    a.x = expf(a.x - bm); a.y = expf(a.y - bm); a.z = expf(a.z - bm); a.w = expf(a.w - bm);
    b.x = expf(b.x - bm); b.y = expf(b.y - bm); b.z = expf(b.z - bm); b.w = expf(b.w - bm);

    float sm = a.x + a.y + a.z + a.w + b.x + b.y + b.z + b.w;
    #pragma unroll
    for (int o = 16; o > 0; o >>= 1) sm += __shfl_xor_sync(~0u, sm, o);
    if (lane == 0) reds[wid] = sm;
    __syncthreads();
    float bs = reds[0] + reds[1] + reds[2] + reds[3] + reds[4] + reds[5] + reds[6] + reds[7];
    float inv = 1.0f / bs;

    const size_t base = (size_t)blockIdx.x * SEQ;
    unsigned short* PP = (unsigned short*)P;
    ushort4 H;
    H.x = h1(a.x * inv); H.y = h1(a.y * inv);
    H.z = h1(a.z * inv); H.w = h1(a.w * inv);
    *reinterpret_cast<ushort4*>(PP + base + tid * 4) = H;
    H.x = h1(b.x * inv); H.y = h1(b.y * inv);
    H.z = h1(b.z * inv); H.w = h1(b.w * inv);
    *reinterpret_cast<ushort4*>(PP + base + (tid + 256) * 4) = H;
}

// ---------------------------------------------------------------------------
// Launch
// ---------------------------------------------------------------------------
extern "C" void kernel_launch(void* const* d_in, const int* in_sizes, int n_in,
                              void* d_out, int out_size)
{
    (void)in_sizes; (void)n_in; (void)out_size;
    const float* x  = (const float*)d_in[0];
    const float* Wq = (const float*)d_in[1];
    const float* Wk = (const float*)d_in[2];
    const float* Wv = (const float*)d_in[3];
    const float* Wo = (const float*)d_in[4];
    float* out = (float*)d_out;

    __half *xs, *Wt, *Qs, *Ks, *Vt, *Ps, *Os;
    float* S;
    cudaGetSymbolAddress((void**)&xs, g_xs);
    cudaGetSymbolAddress((void**)&Wt, g_Wt);
    cudaGetSymbolAddress((void**)&Qs, g_Qs);
    cudaGetSymbolAddress((void**)&Ks, g_Ks);
    cudaGetSymbolAddress((void**)&Vt, g_Vt);
    cudaGetSymbolAddress((void**)&S,  g_S);
    cudaGetSymbolAddress((void**)&Ps, g_Ps);
    cudaGetSymbolAddress((void**)&Os, g_Os);

    cudaFuncSetAttribute(gemm_mma<0>, cudaFuncAttributeMaxDynamicSharedMemorySize, SMEM_SZ);
    cudaFuncSetAttribute(gemm_mma<2>, cudaFuncAttributeMaxDynamicSharedMemorySize, SMEM_SZ);
    cudaFuncSetAttribute(gemm_qkv,    cudaFuncAttributeMaxDynamicSharedMemorySize, SMEM_SZ);

    const float scale = 1.0f / sqrtf((float)D_MODEL);
    const long sBSS = (long)SEQ * SEQ;          // 4194304
    const long sSD  = (long)SEQ * D_MODEL;      // 4194304

    // all conversions in one launch (x conv + 4 weight transposes)
    convall_kernel<<<24576, 256>>>(x, Wq, Wk, Wv, Wo, xs, Wt);

    const dim3 gQKV(D_MODEL / 128, MROWS / 128, 3);    // (16, 32, 3) = 1536 CTAs
    const dim3 gProj(D_MODEL / 128, MROWS / 128, 1);   // (16, 32)
    const dim3 gAttn(SEQ / 128, SEQ / 128, BATCH);     // (16, 16, 2)

    // Q, K, V projections in one launch
    gemm_qkv<<<gQKV, GTHR, SMEM_SZ>>>(xs, Wt, Qs, Ks, Vt);
    // scores = scale * Q @ K^T  (fp32 epilogue)
    gemm_mma<0><<<gAttn, GTHR, SMEM_SZ>>>(Qs, Ks,
                                          S, nullptr, sSD, sSD, sBSS, scale);
    // softmax -> P fp16
    softmax_kernel<<<BATCH * SEQ, 256>>>(S, Ps);
    // O = P @ V  (B operand = V^T)
    gemm_mma<2><<<gAttn, GTHR, SMEM_SZ>>>(Ps, Vt,
                                          nullptr, Os, sBSS, sSD, sSD, 1.0f);
    // out = O @ W_o  (fp32 epilogue)
    gemm_mma<0><<<gProj, GTHR, SMEM_SZ>>>(Os, Wt + 3 * WELEMS,
                                          out, nullptr, 0, 0, 0, 1.0f);
}